// round 3
// baseline (speedup 1.0000x reference)
#include <cuda_runtime.h>
#include <math.h>

#define B_  2
#define S_  2048
#define D_  2048
#define H_  16
#define HD_ 128
#define M_  (B_*S_)      // 4096 rows total

#define TBM 128
#define TBN 128
#define TBK 16

// ---------------- scratch (device globals; no allocation allowed) ----------------
__device__ float g_Q[(size_t)M_*D_];
__device__ float g_K[(size_t)M_*D_];
__device__ float g_V[(size_t)M_*D_];
__device__ float g_AO[(size_t)M_*D_];
__device__ float g_P[(size_t)B_*H_*S_*S_];     // 512 MB score/prob matrix
__device__ float g_cos[S_*64];
__device__ float g_sin[S_*64];

// ---------------- generic C = A * B^T, batched with composite z-offsets ----------
// offset(z) = (z/zdiv)*s?o + (z%zdiv)*s?i
__global__ __launch_bounds__(256)
void sgemm_abt(const float* __restrict__ A, const float* __restrict__ B,
               float* __restrict__ C,
               int M, int N, int K, int lda, int ldb, int ldc,
               int zdiv,
               long long sAo, long long sAi,
               long long sBo, long long sBi,
               long long sCo, long long sCi,
               int causalSkip)
{
    int z = blockIdx.z;
    int zo = z / zdiv, zi = z % zdiv;
    A += zo * sAo + zi * sAi;
    B += zo * sBo + zi * sBi;
    C += zo * sCo + zi * sCi;

    int rowBase = blockIdx.y * TBM;
    int colBase = blockIdx.x * TBN;
    if (causalSkip && colBase > rowBase + TBM - 1) return;   // fully above diagonal

    __shared__ float As[TBK][TBM + 4];
    __shared__ float Bs[TBK][TBN + 4];

    int tid = threadIdx.x;
    int tx = tid & 15, ty = tid >> 4;

    float acc[8][8];
    #pragma unroll
    for (int i = 0; i < 8; i++)
        #pragma unroll
        for (int j = 0; j < 8; j++) acc[i][j] = 0.f;

    for (int k0 = 0; k0 < K; k0 += TBK) {
        #pragma unroll
        for (int i = 0; i < 8; i++) {
            int l = tid + i * 256;
            int r = l >> 4, c = l & 15;
            As[c][r] = A[(long long)(rowBase + r) * lda + (k0 + c)];
        }
        #pragma unroll
        for (int i = 0; i < 8; i++) {
            int l = tid + i * 256;
            int r = l >> 4, c = l & 15;
            Bs[c][r] = B[(long long)(colBase + r) * ldb + (k0 + c)];
        }
        __syncthreads();
        #pragma unroll
        for (int kk = 0; kk < TBK; kk++) {
            float4 a0 = *(const float4*)&As[kk][ty * 8];
            float4 a1 = *(const float4*)&As[kk][ty * 8 + 4];
            float4 b0 = *(const float4*)&Bs[kk][tx * 8];
            float4 b1 = *(const float4*)&Bs[kk][tx * 8 + 4];
            float a[8] = {a0.x, a0.y, a0.z, a0.w, a1.x, a1.y, a1.z, a1.w};
            float b[8] = {b0.x, b0.y, b0.z, b0.w, b1.x, b1.y, b1.z, b1.w};
            #pragma unroll
            for (int i = 0; i < 8; i++)
                #pragma unroll
                for (int j = 0; j < 8; j++)
                    acc[i][j] = fmaf(a[i], b[j], acc[i][j]);
        }
        __syncthreads();
    }
    #pragma unroll
    for (int i = 0; i < 8; i++) {
        float4* cp = (float4*)&C[(long long)(rowBase + ty * 8 + i) * ldc + colBase + tx * 8];
        cp[0] = make_float4(acc[i][0], acc[i][1], acc[i][2], acc[i][3]);
        cp[1] = make_float4(acc[i][4], acc[i][5], acc[i][6], acc[i][7]);
    }
}

// ---------------- RoPE tables (double precision once per launch) -----------------
__global__ void rope_tables()
{
    int i = blockIdx.x * blockDim.x + threadIdx.x;
    if (i >= S_ * 64) return;
    int d = i & 63;
    int s = i >> 6;
    double inv = pow(10000.0, -(double)d / 64.0);
    double ang = (double)s * inv;
    g_cos[i] = (float)cos(ang);
    g_sin[i] = (float)sin(ang);
}

// ---------------- apply RoPE in place to Q and K ---------------------------------
__global__ void rope_apply()
{
    size_t i = (size_t)blockIdx.x * blockDim.x + threadIdx.x;
    if (i >= (size_t)M_ * H_ * 64) return;
    int d = (int)(i & 63);
    int h = (int)((i >> 6) & (H_ - 1));
    int m = (int)(i >> 10);                 // 64*16 pairs per row
    int s = m & (S_ - 1);
    float c  = g_cos[s * 64 + d];
    float sn = g_sin[s * 64 + d];
    size_t base = (size_t)m * D_ + h * HD_ + d;
    float q1 = g_Q[base], q2 = g_Q[base + 64];
    g_Q[base]      = q1 * c - q2 * sn;
    g_Q[base + 64] = q2 * c + q1 * sn;
    float k1 = g_K[base], k2 = g_K[base + 64];
    g_K[base]      = k1 * c - k2 * sn;
    g_K[base + 64] = k2 * c + k1 * sn;
}

// ---------------- causal softmax: one warp per row -------------------------------
__global__ void softmax_rows()
{
    int gw   = (blockIdx.x * blockDim.x + threadIdx.x) >> 5;
    int lane = threadIdx.x & 31;
    if (gw >= B_ * H_ * S_) return;
    int s  = gw & (S_ - 1);
    int bh = gw >> 11;                       // / S_
    float* row = g_P + (size_t)bh * S_ * S_ + (size_t)s * S_;
    const float scale = 0.08838834764831845f;   // 1/sqrt(128)
    int n = s + 1;

    float mx = -3.4e38f;
    for (int j = lane; j < n; j += 32) mx = fmaxf(mx, row[j] * scale);
    #pragma unroll
    for (int o = 16; o; o >>= 1) mx = fmaxf(mx, __shfl_xor_sync(0xffffffffu, mx, o));

    float sum = 0.f;
    for (int j = lane; j < n; j += 32) sum += __expf(row[j] * scale - mx);
    #pragma unroll
    for (int o = 16; o; o >>= 1) sum += __shfl_xor_sync(0xffffffffu, sum, o);

    float inv = 1.f / sum;
    for (int j = lane; j < n; j += 32) row[j] = __expf(row[j] * scale - mx) * inv;
}

// ---------------- out = P * V  (causal-truncated K loop, masked loads) ----------
__global__ __launch_bounds__(256)
void gemm_pv()
{
    int z = blockIdx.z;                      // b*H + h
    int b = z >> 4, h = z & 15;
    const float* __restrict__ Pz = g_P  + (size_t)z * S_ * S_;
    const float* __restrict__ Vz = g_V  + (size_t)b * S_ * D_ + h * HD_;
    float*       __restrict__ Cz = g_AO + (size_t)b * S_ * D_ + h * HD_;

    int rowBase = blockIdx.y * TBM;

    __shared__ float As[TBK][TBM + 4];
    __shared__ float Bs[TBK][HD_ + 4];

    int tid = threadIdx.x;
    int tx = tid & 15, ty = tid >> 4;

    float acc[8][8];
    #pragma unroll
    for (int i = 0; i < 8; i++)
        #pragma unroll
        for (int j = 0; j < 8; j++) acc[i][j] = 0.f;

    int kmax = rowBase + TBM;                // causal: only k <= rowBase+127 used
    for (int k0 = 0; k0 < kmax; k0 += TBK) {
        #pragma unroll
        for (int i = 0; i < 8; i++) {
            int l = tid + i * 256;
            int r = l >> 4, c = l & 15;
            int kcol = k0 + c, row = rowBase + r;
            As[c][r] = (kcol <= row) ? Pz[(size_t)row * S_ + kcol] : 0.f;
        }
        #pragma unroll
        for (int i = 0; i < 8; i++) {
            int l = tid + i * 256;
            int kk = l >> 7, n = l & 127;
            Bs[kk][n] = Vz[(size_t)(k0 + kk) * D_ + n];
        }
        __syncthreads();
        #pragma unroll
        for (int kk = 0; kk < TBK; kk++) {
            float4 a0 = *(const float4*)&As[kk][ty * 8];
            float4 a1 = *(const float4*)&As[kk][ty * 8 + 4];
            float4 b0 = *(const float4*)&Bs[kk][tx * 8];
            float4 b1 = *(const float4*)&Bs[kk][tx * 8 + 4];
            float a[8] = {a0.x, a0.y, a0.z, a0.w, a1.x, a1.y, a1.z, a1.w};
            float b[8] = {b0.x, b0.y, b0.z, b0.w, b1.x, b1.y, b1.z, b1.w};
            #pragma unroll
            for (int i = 0; i < 8; i++)
                #pragma unroll
                for (int j = 0; j < 8; j++)
                    acc[i][j] = fmaf(a[i], b[j], acc[i][j]);
        }
        __syncthreads();
    }
    #pragma unroll
    for (int i = 0; i < 8; i++) {
        float4* cp = (float4*)&Cz[(size_t)(rowBase + ty * 8 + i) * D_ + tx * 8];
        cp[0] = make_float4(acc[i][0], acc[i][1], acc[i][2], acc[i][3]);
        cp[1] = make_float4(acc[i][4], acc[i][5], acc[i][6], acc[i][7]);
    }
}

// ---------------- launch --------------------------------------------------------
extern "C" void kernel_launch(void* const* d_in, const int* in_sizes, int n_in,
                              void* d_out, int out_size)
{
    const float* x  = (const float*)d_in[0];
    const float* Wq = (const float*)d_in[1];
    const float* Wk = (const float*)d_in[2];
    const float* Wv = (const float*)d_in[3];
    const float* Wo = (const float*)d_in[4];
    float* out = (float*)d_out;

    float *Qp, *Kp, *Vp, *AOp, *Pp;
    cudaGetSymbolAddress((void**)&Qp,  g_Q);
    cudaGetSymbolAddress((void**)&Kp,  g_K);
    cudaGetSymbolAddress((void**)&Vp,  g_V);
    cudaGetSymbolAddress((void**)&AOp, g_AO);
    cudaGetSymbolAddress((void**)&Pp,  g_P);

    dim3 blk(256);

    // 1) Q/K/V projections: (M_, D_) = x(M_,D_) * W^T
    dim3 gProj(D_ / TBN, M_ / TBM, 1);
    sgemm_abt<<<gProj, blk>>>(x, Wq, Qp, M_, D_, D_, D_, D_, D_,
                              1, 0, 0, 0, 0, 0, 0, 0);
    sgemm_abt<<<gProj, blk>>>(x, Wk, Kp, M_, D_, D_, D_, D_, D_,
                              1, 0, 0, 0, 0, 0, 0, 0);
    sgemm_abt<<<gProj, blk>>>(x, Wv, Vp, M_, D_, D_, D_, D_, D_,
                              1, 0, 0, 0, 0, 0, 0, 0);

    // 2) RoPE
    rope_tables<<<(S_ * 64 + 255) / 256, blk>>>();
    rope_apply<<<((size_t)M_ * H_ * 64 + 255) / 256, blk>>>();

    // 3) scores = Q K^T per (b,h), causal block skip
    dim3 gScore(S_ / TBN, S_ / TBM, B_ * H_);
    sgemm_abt<<<gScore, blk>>>(Qp, Kp, Pp, S_, S_, HD_, D_, D_, S_,
                               H_,
                               (long long)S_ * D_, (long long)HD_,
                               (long long)S_ * D_, (long long)HD_,
                               (long long)H_ * S_ * S_, (long long)S_ * S_,
                               1);

    // 4) causal softmax (warp per row)
    {
        long long warps = (long long)B_ * H_ * S_;
        long long threads = warps * 32;
        softmax_rows<<<(unsigned)((threads + 255) / 256), blk>>>();
    }

    // 5) attn_out = P * V
    dim3 gPV(1, S_ / TBM, B_ * H_);
    gemm_pv<<<gPV, blk>>>();

    // 6) final projection: out = AO * Wo^T
    sgemm_abt<<<gProj, blk>>>(AOp, Wo, out, M_, D_, D_, D_, D_, D_,
                              1, 0, 0, 0, 0, 0, 0, 0);
}

// round 5
// speedup vs baseline: 2.5631x; 2.5631x over previous
#include <cuda_runtime.h>
#include <cuda_bf16.h>
#include <math.h>
#include <stdint.h>

#define B_  2
#define S_  2048
#define D_  2048
#define H_  16
#define HD_ 128
#define M_  (B_*S_)      // 4096 rows total

// ---------------- scratch (device globals; no allocation allowed) ----------------
__device__ float g_Q[(size_t)M_*D_];
__device__ float g_K[(size_t)M_*D_];
__device__ float g_V[(size_t)M_*D_];
__device__ float g_AO[(size_t)M_*D_];
__device__ float g_P[(size_t)B_*H_*S_*S_];     // 512 MB score/prob matrix
__device__ float g_cos[S_*64];
__device__ float g_sin[S_*64];

// ---------------- small helpers --------------------------------------------------
__device__ __forceinline__ uint32_t smem_u32(const void* p) {
    return (uint32_t)__cvta_generic_to_shared(p);
}

__device__ __forceinline__ void ldsm4(uint32_t r[4], uint32_t addr) {
    asm volatile("ldmatrix.sync.aligned.m8n8.x4.shared.b16 {%0,%1,%2,%3},[%4];"
                 : "=r"(r[0]), "=r"(r[1]), "=r"(r[2]), "=r"(r[3]) : "r"(addr));
}
__device__ __forceinline__ void ldsm4t(uint32_t r[4], uint32_t addr) {
    asm volatile("ldmatrix.sync.aligned.m8n8.x4.trans.shared.b16 {%0,%1,%2,%3},[%4];"
                 : "=r"(r[0]), "=r"(r[1]), "=r"(r[2]), "=r"(r[3]) : "r"(addr));
}

__device__ __forceinline__ void mma_bf16(float d[4], const uint32_t a[4], const uint32_t b[2]) {
    asm volatile(
        "mma.sync.aligned.m16n8k16.row.col.f32.bf16.bf16.f32 "
        "{%0,%1,%2,%3},{%4,%5,%6,%7},{%8,%9},{%0,%1,%2,%3};"
        : "+f"(d[0]), "+f"(d[1]), "+f"(d[2]), "+f"(d[3])
        : "r"(a[0]), "r"(a[1]), "r"(a[2]), "r"(a[3]), "r"(b[0]), "r"(b[1]));
}

// split fp32 -> bf16 hi + bf16 lo (residual). (a_hi+a_lo)(b_hi+b_lo) with 3 products
// leaves only the lo*lo term (~2^-18 relative) unaccounted.
__device__ __forceinline__ void split2(float x0, float x1, uint32_t &h, uint32_t &l) {
    __nv_bfloat16 h0 = __float2bfloat16(x0);
    __nv_bfloat16 h1 = __float2bfloat16(x1);
    __nv_bfloat16 l0 = __float2bfloat16(x0 - __bfloat162float(h0));
    __nv_bfloat16 l1 = __float2bfloat16(x1 - __bfloat162float(h1));
    __nv_bfloat162 hp = __halves2bfloat162(h0, h1);   // .x = low half
    __nv_bfloat162 lp = __halves2bfloat162(l0, l1);
    h = *reinterpret_cast<uint32_t*>(&hp);
    l = *reinterpret_cast<uint32_t*>(&lp);
}

// ============================================================================
// C = A * B^T with bf16-split tensor-core mma.
// A: [m][k] row-major (lda), B: [n][k] row-major (ldb), C: [m][n] (ldc).
// CTA tile 128x128, k-tile 64 (4 x k16 mma steps), 8 warps (2m x 4n), warp 64x32.
// smem (dynamic 64KB): As_h, As_l, Bs_h, Bs_l each 128x64 bf16, XOR-swizzled.
// ============================================================================
__global__ __launch_bounds__(256)
void hgemm_abt(const float* __restrict__ A, const float* __restrict__ Bm,
               float* __restrict__ C,
               int K, int lda, int ldb, int ldc,
               int zdiv,
               long long sAo, long long sAi,
               long long sBo, long long sBi,
               long long sCo, long long sCi,
               int causalSkip)
{
    int z = blockIdx.z;
    int zo = z / zdiv, zi = z - zo * zdiv;
    A  += zo * sAo + zi * sAi;
    Bm += zo * sBo + zi * sBi;
    C  += zo * sCo + zi * sCi;

    int rowBase = blockIdx.y * 128;
    int colBase = blockIdx.x * 128;
    if (causalSkip && colBase > rowBase) return;     // tile fully above diagonal

    extern __shared__ __align__(16) char sraw[];
    uint32_t* As_h = (uint32_t*)sraw;                // 4096 pairs (16KB)
    uint32_t* As_l = As_h + 4096;
    uint32_t* Bs_h = As_l + 4096;
    uint32_t* Bs_l = Bs_h + 4096;

    int tid = threadIdx.x, lane = tid & 31, w = tid >> 5;
    int wm = w >> 2, wn = w & 3;
    int lr = lane & 7, grp = lane >> 3;

    uint32_t a_h = smem_u32(As_h), a_l = smem_u32(As_l);
    uint32_t b_h = smem_u32(Bs_h), b_l = smem_u32(Bs_l);

    // per-lane ldmatrix geometry (addresses into 128B rows, 16B swizzled chunks)
    int agk = grp >> 1;                // A: grp bit1 -> k-chunk
    uint32_t arow[4], arx[4];
    #pragma unroll
    for (int s = 0; s < 4; s++) {
        int r = wm * 64 + s * 16 + ((grp & 1) << 3) + lr;
        arow[s] = (uint32_t)r << 7;
        arx[s]  = r & 7;
    }
    int bgk = grp & 1;                 // B: grp bit0 -> k-chunk
    uint32_t brow[2], brx[2];
    #pragma unroll
    for (int p = 0; p < 2; p++) {
        int r = wn * 32 + p * 16 + ((grp >> 1) << 3) + lr;
        brow[p] = (uint32_t)r << 7;
        brx[p]  = r & 7;
    }

    float acc[4][4][4];
    #pragma unroll
    for (int s = 0; s < 4; s++)
        #pragma unroll
        for (int n = 0; n < 4; n++)
            #pragma unroll
            for (int j = 0; j < 4; j++) acc[s][n][j] = 0.f;

    for (int k0 = 0; k0 < K; k0 += 64) {
        // ---- global -> smem with bf16 split (A then B; 8 float4 each) ----
        #pragma unroll
        for (int i = 0; i < 8; i++) {
            int id = tid + (i << 8);
            int r = id >> 4, f4 = id & 15;
            float4 v = *(const float4*)(A + (size_t)(rowBase + r) * lda + k0 + (f4 << 2));
            int idx = (r << 5) + ((((f4 >> 1) ^ (r & 7)) << 2) | ((f4 & 1) << 1));
            uint32_t h0, l0, h1, l1;
            split2(v.x, v.y, h0, l0);
            split2(v.z, v.w, h1, l1);
            *(uint2*)&As_h[idx] = make_uint2(h0, h1);
            *(uint2*)&As_l[idx] = make_uint2(l0, l1);
        }
        #pragma unroll
        for (int i = 0; i < 8; i++) {
            int id = tid + (i << 8);
            int r = id >> 4, f4 = id & 15;
            float4 v = *(const float4*)(Bm + (size_t)(colBase + r) * ldb + k0 + (f4 << 2));
            int idx = (r << 5) + ((((f4 >> 1) ^ (r & 7)) << 2) | ((f4 & 1) << 1));
            uint32_t h0, l0, h1, l1;
            split2(v.x, v.y, h0, l0);
            split2(v.z, v.w, h1, l1);
            *(uint2*)&Bs_h[idx] = make_uint2(h0, h1);
            *(uint2*)&Bs_l[idx] = make_uint2(l0, l1);
        }
        __syncthreads();

        #pragma unroll
        for (int st = 0; st < 4; st++) {
            uint32_t Ah[4][4], Al[4][4], Bh[4][2], Bl[4][2];
            #pragma unroll
            for (int s = 0; s < 4; s++) {
                uint32_t off = arow[s] + ((((st << 1) + agk) ^ arx[s]) << 4);
                ldsm4(Ah[s], a_h + off);
                ldsm4(Al[s], a_l + off);
            }
            #pragma unroll
            for (int p = 0; p < 2; p++) {
                uint32_t off = brow[p] + ((((st << 1) + bgk) ^ brx[p]) << 4);
                uint32_t t[4];
                ldsm4(t, b_h + off);
                Bh[2*p][0] = t[0]; Bh[2*p][1] = t[1];
                Bh[2*p+1][0] = t[2]; Bh[2*p+1][1] = t[3];
                ldsm4(t, b_l + off);
                Bl[2*p][0] = t[0]; Bl[2*p][1] = t[1];
                Bl[2*p+1][0] = t[2]; Bl[2*p+1][1] = t[3];
            }
            #pragma unroll
            for (int s = 0; s < 4; s++)
                #pragma unroll
                for (int n = 0; n < 4; n++) {
                    mma_bf16(acc[s][n], Ah[s], Bh[n]);
                    mma_bf16(acc[s][n], Ah[s], Bl[n]);
                    mma_bf16(acc[s][n], Al[s], Bh[n]);
                }
        }
        __syncthreads();
    }

    // ---- store fp32 accumulators ----
    #pragma unroll
    for (int s = 0; s < 4; s++) {
        int r0 = rowBase + wm * 64 + s * 16 + (lane >> 2);
        #pragma unroll
        for (int n = 0; n < 4; n++) {
            int c0 = colBase + wn * 32 + n * 8 + ((lane & 3) << 1);
            *(float2*)&C[(size_t)r0 * ldc + c0]       = make_float2(acc[s][n][0], acc[s][n][1]);
            *(float2*)&C[(size_t)(r0 + 8) * ldc + c0] = make_float2(acc[s][n][2], acc[s][n][3]);
        }
    }
}

// ============================================================================
// AO = P * V : A = P [m][k] masked causal, B = V [k][n] (n contiguous -> ldsm trans)
// CTA: 128 rows x 128 cols (full head dim), k-tile 64 truncated at rowBase+128.
// ============================================================================
__global__ __launch_bounds__(256)
void hgemm_pv()
{
    int z = blockIdx.z;                      // b*H + h
    int b = z >> 4, h = z & 15;
    const float* __restrict__ Pz = g_P  + (size_t)z * S_ * S_;
    const float* __restrict__ Vz = g_V  + (size_t)b * S_ * D_ + h * HD_;
    float*       __restrict__ Cz = g_AO + (size_t)b * S_ * D_ + h * HD_;

    int rowBase = blockIdx.y * 128;

    extern __shared__ __align__(16) char sraw[];
    uint32_t* As_h = (uint32_t*)sraw;        // P tile 128x64: 4096 pairs
    uint32_t* As_l = As_h + 4096;
    uint32_t* Bs_h = As_l + 4096;            // V tile 64x128: 4096 pairs
    uint32_t* Bs_l = Bs_h + 4096;

    int tid = threadIdx.x, lane = tid & 31, w = tid >> 5;
    int wm = w >> 2, wn = w & 3;
    int lr = lane & 7, grp = lane >> 3;

    uint32_t a_h = smem_u32(As_h), a_l = smem_u32(As_l);
    uint32_t b_h = smem_u32(Bs_h), b_l = smem_u32(Bs_l);

    int agk = grp >> 1;
    uint32_t arow[4], arx[4];
    #pragma unroll
    for (int s = 0; s < 4; s++) {
        int r = wm * 64 + s * 16 + ((grp & 1) << 3) + lr;
        arow[s] = (uint32_t)r << 7;
        arx[s]  = r & 7;
    }
    // V (trans) geometry: rows are k (256B rows = 16 chunks of 16B)
    int krb = ((grp & 1) << 3) + lr;         // k-row within k16 step
    uint32_t bvoff[2];
    #pragma unroll
    for (int p = 0; p < 2; p++) {
        int nc = wn * 4 + p * 2 + (grp >> 1);           // 16B chunk along n
        bvoff[p] = ((uint32_t)krb << 8) + (uint32_t)((nc ^ (krb & 7)) << 4);
    }

    float acc[4][4][4];
    #pragma unroll
    for (int s = 0; s < 4; s++)
        #pragma unroll
        for (int n = 0; n < 4; n++)
            #pragma unroll
            for (int j = 0; j < 4; j++) acc[s][n][j] = 0.f;

    int kmax = rowBase + 128;
    for (int k0 = 0; k0 < kmax; k0 += 64) {
        // ---- P tile (masked causal) ----
        #pragma unroll
        for (int i = 0; i < 8; i++) {
            int id = tid + (i << 8);
            int r = id >> 4, f4 = id & 15;
            int grow = rowBase + r;
            int kc = k0 + (f4 << 2);
            float4 v = *(const float4*)(Pz + (size_t)grow * S_ + kc);
            if (kc + 0 > grow) v.x = 0.f;
            if (kc + 1 > grow) v.y = 0.f;
            if (kc + 2 > grow) v.z = 0.f;
            if (kc + 3 > grow) v.w = 0.f;
            int idx = (r << 5) + ((((f4 >> 1) ^ (r & 7)) << 2) | ((f4 & 1) << 1));
            uint32_t h0, l0, h1, l1;
            split2(v.x, v.y, h0, l0);
            split2(v.z, v.w, h1, l1);
            *(uint2*)&As_h[idx] = make_uint2(h0, h1);
            *(uint2*)&As_l[idx] = make_uint2(l0, l1);
        }
        // ---- V tile 64(k) x 128(n) ----
        #pragma unroll
        for (int i = 0; i < 8; i++) {
            int id = tid + (i << 8);
            int kr = id >> 5, f4 = id & 31;
            float4 v = *(const float4*)(Vz + (size_t)(k0 + kr) * D_ + (f4 << 2));
            int idx = (kr << 6) + ((((f4 >> 1) ^ (kr & 7)) << 2) | ((f4 & 1) << 1));
            uint32_t h0, l0, h1, l1;
            split2(v.x, v.y, h0, l0);
            split2(v.z, v.w, h1, l1);
            *(uint2*)&Bs_h[idx] = make_uint2(h0, h1);
            *(uint2*)&Bs_l[idx] = make_uint2(l0, l1);
        }
        __syncthreads();

        #pragma unroll
        for (int st = 0; st < 4; st++) {
            uint32_t Ah[4][4], Al[4][4], Bh[4][2], Bl[4][2];
            #pragma unroll
            for (int s = 0; s < 4; s++) {
                uint32_t off = arow[s] + ((((st << 1) + agk) ^ arx[s]) << 4);
                ldsm4(Ah[s], a_h + off);
                ldsm4(Al[s], a_l + off);
            }
            #pragma unroll
            for (int p = 0; p < 2; p++) {
                uint32_t off = ((uint32_t)st << 12) + bvoff[p];   // st*16 k-rows * 256B
                uint32_t t[4];
                ldsm4t(t, b_h + off);
                Bh[2*p][0] = t[0]; Bh[2*p][1] = t[1];
                Bh[2*p+1][0] = t[2]; Bh[2*p+1][1] = t[3];
                ldsm4t(t, b_l + off);
                Bl[2*p][0] = t[0]; Bl[2*p][1] = t[1];
                Bl[2*p+1][0] = t[2]; Bl[2*p+1][1] = t[3];
            }
            #pragma unroll
            for (int s = 0; s < 4; s++)
                #pragma unroll
                for (int n = 0; n < 4; n++) {
                    mma_bf16(acc[s][n], Ah[s], Bh[n]);
                    mma_bf16(acc[s][n], Ah[s], Bl[n]);
                    mma_bf16(acc[s][n], Al[s], Bh[n]);
                }
        }
        __syncthreads();
    }

    #pragma unroll
    for (int s = 0; s < 4; s++) {
        int r0 = rowBase + wm * 64 + s * 16 + (lane >> 2);
        #pragma unroll
        for (int n = 0; n < 4; n++) {
            int c0 = wn * 32 + n * 8 + ((lane & 3) << 1);
            *(float2*)&Cz[(size_t)r0 * D_ + c0]       = make_float2(acc[s][n][0], acc[s][n][1]);
            *(float2*)&Cz[(size_t)(r0 + 8) * D_ + c0] = make_float2(acc[s][n][2], acc[s][n][3]);
        }
    }
}

// ---------------- RoPE tables (double precision once per launch) -----------------
__global__ void rope_tables()
{
    int i = blockIdx.x * blockDim.x + threadIdx.x;
    if (i >= S_ * 64) return;
    int d = i & 63;
    int s = i >> 6;
    double inv = pow(10000.0, -(double)d / 64.0);
    double ang = (double)s * inv;
    g_cos[i] = (float)cos(ang);
    g_sin[i] = (float)sin(ang);
}

// ---------------- apply RoPE in place to Q and K ---------------------------------
__global__ void rope_apply()
{
    size_t i = (size_t)blockIdx.x * blockDim.x + threadIdx.x;
    if (i >= (size_t)M_ * H_ * 64) return;
    int d = (int)(i & 63);
    int h = (int)((i >> 6) & (H_ - 1));
    int m = (int)(i >> 10);
    int s = m & (S_ - 1);
    float c  = g_cos[s * 64 + d];
    float sn = g_sin[s * 64 + d];
    size_t base = (size_t)m * D_ + h * HD_ + d;
    float q1 = g_Q[base], q2 = g_Q[base + 64];
    g_Q[base]      = q1 * c - q2 * sn;
    g_Q[base + 64] = q2 * c + q1 * sn;
    float k1 = g_K[base], k2 = g_K[base + 64];
    g_K[base]      = k1 * c - k2 * sn;
    g_K[base + 64] = k2 * c + k1 * sn;
}

// ---------------- causal softmax: one warp per row -------------------------------
__global__ void softmax_rows()
{
    int gw   = (blockIdx.x * blockDim.x + threadIdx.x) >> 5;
    int lane = threadIdx.x & 31;
    if (gw >= B_ * H_ * S_) return;
    int s  = gw & (S_ - 1);
    int bh = gw >> 11;
    float* row = g_P + (size_t)bh * S_ * S_ + (size_t)s * S_;
    const float scale = 0.08838834764831845f;   // 1/sqrt(128)
    int n = s + 1;

    float mx = -3.4e38f;
    for (int j = lane; j < n; j += 32) mx = fmaxf(mx, row[j] * scale);
    #pragma unroll
    for (int o = 16; o; o >>= 1) mx = fmaxf(mx, __shfl_xor_sync(0xffffffffu, mx, o));

    float sum = 0.f;
    for (int j = lane; j < n; j += 32) sum += __expf(row[j] * scale - mx);
    #pragma unroll
    for (int o = 16; o; o >>= 1) sum += __shfl_xor_sync(0xffffffffu, sum, o);

    float inv = 1.f / sum;
    for (int j = lane; j < n; j += 32) row[j] = __expf(row[j] * scale - mx) * inv;
}

// ---------------- launch --------------------------------------------------------
extern "C" void kernel_launch(void* const* d_in, const int* in_sizes, int n_in,
                              void* d_out, int out_size)
{
    const float* x  = (const float*)d_in[0];
    const float* Wq = (const float*)d_in[1];
    const float* Wk = (const float*)d_in[2];
    const float* Wv = (const float*)d_in[3];
    const float* Wo = (const float*)d_in[4];
    float* out = (float*)d_out;

    float *Qp, *Kp, *Vp, *AOp, *Pp;
    cudaGetSymbolAddress((void**)&Qp,  g_Q);
    cudaGetSymbolAddress((void**)&Kp,  g_K);
    cudaGetSymbolAddress((void**)&Vp,  g_V);
    cudaGetSymbolAddress((void**)&AOp, g_AO);
    cudaGetSymbolAddress((void**)&Pp,  g_P);

    cudaFuncSetAttribute(hgemm_abt, cudaFuncAttributeMaxDynamicSharedMemorySize, 65536);
    cudaFuncSetAttribute(hgemm_pv,  cudaFuncAttributeMaxDynamicSharedMemorySize, 65536);

    dim3 blk(256);

    // 1) Q/K/V projections: (4096 x 2048) = x * W^T
    dim3 gProj(D_ / 128, M_ / 128, 1);
    hgemm_abt<<<gProj, blk, 65536>>>(x, Wq, Qp, D_, D_, D_, D_, 1, 0,0,0,0,0,0, 0);
    hgemm_abt<<<gProj, blk, 65536>>>(x, Wk, Kp, D_, D_, D_, D_, 1, 0,0,0,0,0,0, 0);
    hgemm_abt<<<gProj, blk, 65536>>>(x, Wv, Vp, D_, D_, D_, D_, 1, 0,0,0,0,0,0, 0);

    // 2) RoPE
    rope_tables<<<(S_ * 64 + 255) / 256, blk>>>();
    rope_apply<<<((size_t)M_ * H_ * 64 + 255) / 256, blk>>>();

    // 3) scores = Q K^T per (b,h), causal block skip
    dim3 gScore(S_ / 128, S_ / 128, B_ * H_);
    hgemm_abt<<<gScore, blk, 65536>>>(Qp, Kp, Pp, HD_, D_, D_, S_,
                                      H_,
                                      (long long)S_ * D_, (long long)HD_,
                                      (long long)S_ * D_, (long long)HD_,
                                      (long long)H_ * S_ * S_, (long long)S_ * S_,
                                      1);

    // 4) causal softmax (warp per row)
    {
        long long warps = (long long)B_ * H_ * S_;
        long long threads = warps * 32;
        softmax_rows<<<(unsigned)((threads + 255) / 256), blk>>>();
    }

    // 5) attn_out = P * V
    dim3 gPV(1, S_ / 128, B_ * H_);
    hgemm_pv<<<gPV, blk, 65536>>>();

    // 6) final projection: out = AO * Wo^T
    hgemm_abt<<<gProj, blk, 65536>>>(AOp, Wo, out, D_, D_, D_, D_, 1, 0,0,0,0,0,0, 0);
}

// round 6
// speedup vs baseline: 3.4119x; 1.3312x over previous
#include <cuda_runtime.h>
#include <cuda_bf16.h>
#include <math.h>
#include <stdint.h>

#define B_  2
#define S_  2048
#define D_  2048
#define H_  16
#define HD_ 128
#define M_  (B_*S_)      // 4096 rows total

// ---------------- scratch (device globals; no allocation allowed) ----------------
__device__ float g_Q[(size_t)M_*D_];                 // fp32 proj out (pre-rope)
__device__ float g_K[(size_t)M_*D_];
__device__ float g_P[(size_t)B_*H_*S_*S_];           // fp32 scores
__device__ float g_cos[S_*64];
__device__ float g_sin[S_*64];

// planar bf16 hi/lo split operands
__device__ __nv_bfloat16 g_xh[(size_t)M_*D_],  g_xl[(size_t)M_*D_];
__device__ __nv_bfloat16 g_Wqh[(size_t)D_*D_], g_Wql[(size_t)D_*D_];
__device__ __nv_bfloat16 g_Wkh[(size_t)D_*D_], g_Wkl[(size_t)D_*D_];
__device__ __nv_bfloat16 g_Wvh[(size_t)D_*D_], g_Wvl[(size_t)D_*D_];
__device__ __nv_bfloat16 g_Woh[(size_t)D_*D_], g_Wol[(size_t)D_*D_];
__device__ __nv_bfloat16 g_Qh[(size_t)M_*D_],  g_Ql[(size_t)M_*D_];
__device__ __nv_bfloat16 g_Kh[(size_t)M_*D_],  g_Kl[(size_t)M_*D_];
__device__ __nv_bfloat16 g_Vh[(size_t)M_*D_],  g_Vl[(size_t)M_*D_];
__device__ __nv_bfloat16 g_Ph[(size_t)B_*H_*S_*S_], g_Pl[(size_t)B_*H_*S_*S_];
__device__ __nv_bfloat16 g_AOh[(size_t)M_*D_], g_AOl[(size_t)M_*D_];

// ---------------- helpers ---------------------------------------------------------
__device__ __forceinline__ uint32_t smem_u32(const void* p) {
    return (uint32_t)__cvta_generic_to_shared(p);
}
__device__ __forceinline__ void cpa16(uint32_t dst, const void* src) {
    asm volatile("cp.async.cg.shared.global [%0],[%1],16;" :: "r"(dst), "l"(src));
}
__device__ __forceinline__ void cpa_commit() { asm volatile("cp.async.commit_group;"); }
template<int N> __device__ __forceinline__ void cpa_wait() {
    asm volatile("cp.async.wait_group %0;" :: "n"(N));
}
__device__ __forceinline__ void ldsm4(uint32_t r[4], uint32_t addr) {
    asm volatile("ldmatrix.sync.aligned.m8n8.x4.shared.b16 {%0,%1,%2,%3},[%4];"
                 : "=r"(r[0]), "=r"(r[1]), "=r"(r[2]), "=r"(r[3]) : "r"(addr));
}
__device__ __forceinline__ void ldsm4t(uint32_t r[4], uint32_t addr) {
    asm volatile("ldmatrix.sync.aligned.m8n8.x4.trans.shared.b16 {%0,%1,%2,%3},[%4];"
                 : "=r"(r[0]), "=r"(r[1]), "=r"(r[2]), "=r"(r[3]) : "r"(addr));
}
__device__ __forceinline__ void mma_bf16(float d[4], const uint32_t a[4], const uint32_t b[2]) {
    asm volatile(
        "mma.sync.aligned.m16n8k16.row.col.f32.bf16.bf16.f32 "
        "{%0,%1,%2,%3},{%4,%5,%6,%7},{%8,%9},{%0,%1,%2,%3};"
        : "+f"(d[0]), "+f"(d[1]), "+f"(d[2]), "+f"(d[3])
        : "r"(a[0]), "r"(a[1]), "r"(a[2]), "r"(a[3]), "r"(b[0]), "r"(b[1]));
}
__device__ __forceinline__ void split2(float x0, float x1, uint32_t &h, uint32_t &l) {
    __nv_bfloat16 h0 = __float2bfloat16(x0);
    __nv_bfloat16 h1 = __float2bfloat16(x1);
    __nv_bfloat16 l0 = __float2bfloat16(x0 - __bfloat162float(h0));
    __nv_bfloat16 l1 = __float2bfloat16(x1 - __bfloat162float(h1));
    __nv_bfloat162 hp = __halves2bfloat162(h0, h1);
    __nv_bfloat162 lp = __halves2bfloat162(l0, l1);
    h = *reinterpret_cast<uint32_t*>(&hp);
    l = *reinterpret_cast<uint32_t*>(&lp);
}

// ---------------- elementwise fp32 -> (hi,lo) convert -----------------------------
__global__ __launch_bounds__(256)
void split_arr(const float4* __restrict__ src,
               uint2* __restrict__ h, uint2* __restrict__ l, int n4)
{
    int i = blockIdx.x * blockDim.x + threadIdx.x;
    if (i >= n4) return;
    float4 v = src[i];
    uint32_t h0, l0, h1, l1;
    split2(v.x, v.y, h0, l0);
    split2(v.z, v.w, h1, l1);
    h[i] = make_uint2(h0, h1);
    l[i] = make_uint2(l0, l1);
}

// ============================================================================
// C = A * B^T, A/B pre-split bf16 planar (hi/lo). CTA 128x128, k-tile 64,
// double-buffered cp.async. 8 warps (2m x 4n), warp 64x32.
// smem: 2 stages x { Ah 16K | Al 16K | Bh 16K | Bl 16K } = 128KB.
// outSplit: 0 -> C fp32 ; 1 -> Ch/Cl bf16.
// ============================================================================
__global__ __launch_bounds__(256)
void gemm_bs(const __nv_bfloat16* __restrict__ Agh, const __nv_bfloat16* __restrict__ Agl,
             const __nv_bfloat16* __restrict__ Bgh, const __nv_bfloat16* __restrict__ Bgl,
             float* __restrict__ C,
             __nv_bfloat16* __restrict__ Ch, __nv_bfloat16* __restrict__ Cl,
             int K, int lda, int ldb, int ldc,
             int zdiv,
             long long sAo, long long sAi,
             long long sBo, long long sBi,
             long long sCo, long long sCi,
             int causalSkip, int outSplit)
{
    int z = blockIdx.z;
    int zo = z / zdiv, zi = z - zo * zdiv;
    long long aOff = zo * sAo + zi * sAi;
    long long bOff = zo * sBo + zi * sBi;
    long long cOff = zo * sCo + zi * sCi;
    Agh += aOff; Agl += aOff;
    Bgh += bOff; Bgl += bOff;

    int rowBase = blockIdx.y * 128;
    int colBase = blockIdx.x * 128;
    if (causalSkip && colBase > rowBase) return;

    extern __shared__ __align__(16) char sraw[];
    uint32_t sb = smem_u32(sraw);

    int tid = threadIdx.x, lane = tid & 31, w = tid >> 5;
    int wm = w >> 2, wn = w & 3;
    int lr = lane & 7, grp = lane >> 3;

    // cp.async geometry: 1024 chunks (16B) per 128x64 bf16 tile; 4 per thread
    int cr = tid >> 3, cc = tid & 7;                  // not used directly; per-i below

    int agk = grp >> 1;
    uint32_t arow[4], arx[4];
    #pragma unroll
    for (int s = 0; s < 4; s++) {
        int r = wm * 64 + s * 16 + ((grp & 1) << 3) + lr;
        arow[s] = (uint32_t)r << 7;
        arx[s]  = r & 7;
    }
    int bgk = grp & 1;
    uint32_t brow[2], brx[2];
    #pragma unroll
    for (int p = 0; p < 2; p++) {
        int r = wn * 32 + p * 16 + ((grp >> 1) << 3) + lr;
        brow[p] = (uint32_t)r << 7;
        brx[p]  = r & 7;
    }

    float acc[4][4][4];
    #pragma unroll
    for (int s = 0; s < 4; s++)
        #pragma unroll
        for (int n = 0; n < 4; n++)
            #pragma unroll
            for (int j = 0; j < 4; j++) acc[s][n][j] = 0.f;

    int T = K >> 6;

    // ---- stage loader ----
    auto issue = [&](int t, int stg) {
        uint32_t base = sb + (uint32_t)stg * 65536u;
        int k0 = t << 6;
        #pragma unroll
        for (int i = 0; i < 4; i++) {
            int id = tid + (i << 8);
            int r = id >> 3, c = id & 7;
            uint32_t dst = base + ((uint32_t)r << 7) + (uint32_t)((c ^ (r & 7)) << 4);
            const __nv_bfloat16* src = Agh + (size_t)(rowBase + r) * lda + k0 + (c << 3);
            cpa16(dst, src);
            cpa16(dst + 16384u, Agl + (size_t)(rowBase + r) * lda + k0 + (c << 3));
        }
        #pragma unroll
        for (int i = 0; i < 4; i++) {
            int id = tid + (i << 8);
            int r = id >> 3, c = id & 7;
            uint32_t dst = base + 32768u + ((uint32_t)r << 7) + (uint32_t)((c ^ (r & 7)) << 4);
            cpa16(dst, Bgh + (size_t)(colBase + r) * ldb + k0 + (c << 3));
            cpa16(dst + 16384u, Bgl + (size_t)(colBase + r) * ldb + k0 + (c << 3));
        }
        cpa_commit();
    };

    issue(0, 0);
    for (int t = 0; t < T; t++) {
        int stg = t & 1;
        if (t + 1 < T) { issue(t + 1, stg ^ 1); cpa_wait<1>(); }
        else          { cpa_wait<0>(); }
        __syncthreads();

        uint32_t aH = sb + (uint32_t)stg * 65536u;
        uint32_t aL = aH + 16384u;
        uint32_t bH = aH + 32768u;
        uint32_t bL = aH + 49152u;

        #pragma unroll
        for (int st = 0; st < 4; st++) {
            uint32_t Ah[4][4], Al[4][4], Bh[4][2], Bl[4][2];
            #pragma unroll
            for (int s = 0; s < 4; s++) {
                uint32_t off = arow[s] + ((((st << 1) + agk) ^ arx[s]) << 4);
                ldsm4(Ah[s], aH + off);
                ldsm4(Al[s], aL + off);
            }
            #pragma unroll
            for (int p = 0; p < 2; p++) {
                uint32_t off = brow[p] + ((((st << 1) + bgk) ^ brx[p]) << 4);
                uint32_t tr[4];
                ldsm4(tr, bH + off);
                Bh[2*p][0] = tr[0]; Bh[2*p][1] = tr[1];
                Bh[2*p+1][0] = tr[2]; Bh[2*p+1][1] = tr[3];
                ldsm4(tr, bL + off);
                Bl[2*p][0] = tr[0]; Bl[2*p][1] = tr[1];
                Bl[2*p+1][0] = tr[2]; Bl[2*p+1][1] = tr[3];
            }
            #pragma unroll
            for (int s = 0; s < 4; s++)
                #pragma unroll
                for (int n = 0; n < 4; n++) {
                    mma_bf16(acc[s][n], Ah[s], Bh[n]);
                    mma_bf16(acc[s][n], Ah[s], Bl[n]);
                    mma_bf16(acc[s][n], Al[s], Bh[n]);
                }
        }
        __syncthreads();
    }

    // ---- epilogue ----
    #pragma unroll
    for (int s = 0; s < 4; s++) {
        int r0 = rowBase + wm * 64 + s * 16 + (lane >> 2);
        #pragma unroll
        for (int n = 0; n < 4; n++) {
            int c0 = colBase + wn * 32 + n * 8 + ((lane & 3) << 1);
            if (!outSplit) {
                float* Cb = C + cOff;
                *(float2*)&Cb[(size_t)r0 * ldc + c0]       = make_float2(acc[s][n][0], acc[s][n][1]);
                *(float2*)&Cb[(size_t)(r0 + 8) * ldc + c0] = make_float2(acc[s][n][2], acc[s][n][3]);
            } else {
                __nv_bfloat16* Hb = Ch + cOff;
                __nv_bfloat16* Lb = Cl + cOff;
                uint32_t h0, l0, h1, l1;
                split2(acc[s][n][0], acc[s][n][1], h0, l0);
                split2(acc[s][n][2], acc[s][n][3], h1, l1);
                *(uint32_t*)&Hb[(size_t)r0 * ldc + c0]       = h0;
                *(uint32_t*)&Lb[(size_t)r0 * ldc + c0]       = l0;
                *(uint32_t*)&Hb[(size_t)(r0 + 8) * ldc + c0] = h1;
                *(uint32_t*)&Lb[(size_t)(r0 + 8) * ldc + c0] = l1;
            }
        }
    }
}

// ============================================================================
// AO = P * V : P pre-split (zero-padded causal), V pre-split [k][n].
// k loop truncated at rowBase+128. Split bf16 output.
// smem: 2 stages x { Ph 16K | Pl 16K | Vh 16K | Vl 16K }.
// ============================================================================
__global__ __launch_bounds__(256)
void gemm_pv()
{
    int z = blockIdx.z;
    int b = z >> 4, h = z & 15;
    const __nv_bfloat16* __restrict__ Pzh = g_Ph + (size_t)z * S_ * S_;
    const __nv_bfloat16* __restrict__ Pzl = g_Pl + (size_t)z * S_ * S_;
    const __nv_bfloat16* __restrict__ Vzh = g_Vh + (size_t)b * S_ * D_ + h * HD_;
    const __nv_bfloat16* __restrict__ Vzl = g_Vl + (size_t)b * S_ * D_ + h * HD_;
    __nv_bfloat16* __restrict__ Czh = g_AOh + (size_t)b * S_ * D_ + h * HD_;
    __nv_bfloat16* __restrict__ Czl = g_AOl + (size_t)b * S_ * D_ + h * HD_;

    int rowBase = blockIdx.y * 128;

    extern __shared__ __align__(16) char sraw[];
    uint32_t sb = smem_u32(sraw);

    int tid = threadIdx.x, lane = tid & 31, w = tid >> 5;
    int wm = w >> 2, wn = w & 3;
    int lr = lane & 7, grp = lane >> 3;

    int agk = grp >> 1;
    uint32_t arow[4], arx[4];
    #pragma unroll
    for (int s = 0; s < 4; s++) {
        int r = wm * 64 + s * 16 + ((grp & 1) << 3) + lr;
        arow[s] = (uint32_t)r << 7;
        arx[s]  = r & 7;
    }
    int krb = ((grp & 1) << 3) + lr;
    uint32_t bvoff[2];
    #pragma unroll
    for (int p = 0; p < 2; p++) {
        int nc = wn * 4 + p * 2 + (grp >> 1);
        bvoff[p] = ((uint32_t)krb << 8) + (uint32_t)((nc ^ (krb & 7)) << 4);
    }

    float acc[4][4][4];
    #pragma unroll
    for (int s = 0; s < 4; s++)
        #pragma unroll
        for (int n = 0; n < 4; n++)
            #pragma unroll
            for (int j = 0; j < 4; j++) acc[s][n][j] = 0.f;

    int T = (rowBase >> 6) + 2;

    auto issue = [&](int t, int stg) {
        uint32_t base = sb + (uint32_t)stg * 65536u;
        int k0 = t << 6;
        // P tile 128 rows x 8 chunks
        #pragma unroll
        for (int i = 0; i < 4; i++) {
            int id = tid + (i << 8);
            int r = id >> 3, c = id & 7;
            uint32_t dst = base + ((uint32_t)r << 7) + (uint32_t)((c ^ (r & 7)) << 4);
            cpa16(dst,           Pzh + (size_t)(rowBase + r) * S_ + k0 + (c << 3));
            cpa16(dst + 16384u,  Pzl + (size_t)(rowBase + r) * S_ + k0 + (c << 3));
        }
        // V tile 64 k-rows x 16 chunks
        #pragma unroll
        for (int i = 0; i < 4; i++) {
            int id = tid + (i << 8);
            int kr = id >> 4, c = id & 15;
            uint32_t dst = base + 32768u + ((uint32_t)kr << 8) + (uint32_t)((c ^ (kr & 7)) << 4);
            cpa16(dst,           Vzh + (size_t)(k0 + kr) * D_ + (c << 3));
            cpa16(dst + 16384u,  Vzl + (size_t)(k0 + kr) * D_ + (c << 3));
        }
        cpa_commit();
    };

    issue(0, 0);
    for (int t = 0; t < T; t++) {
        int stg = t & 1;
        if (t + 1 < T) { issue(t + 1, stg ^ 1); cpa_wait<1>(); }
        else          { cpa_wait<0>(); }
        __syncthreads();

        uint32_t aH = sb + (uint32_t)stg * 65536u;
        uint32_t aL = aH + 16384u;
        uint32_t bH = aH + 32768u;
        uint32_t bL = aH + 49152u;

        #pragma unroll
        for (int st = 0; st < 4; st++) {
            uint32_t Ah[4][4], Al[4][4], Bh[4][2], Bl[4][2];
            #pragma unroll
            for (int s = 0; s < 4; s++) {
                uint32_t off = arow[s] + ((((st << 1) + agk) ^ arx[s]) << 4);
                ldsm4(Ah[s], aH + off);
                ldsm4(Al[s], aL + off);
            }
            #pragma unroll
            for (int p = 0; p < 2; p++) {
                uint32_t off = ((uint32_t)st << 12) + bvoff[p];
                uint32_t tr[4];
                ldsm4t(tr, bH + off);
                Bh[2*p][0] = tr[0]; Bh[2*p][1] = tr[1];
                Bh[2*p+1][0] = tr[2]; Bh[2*p+1][1] = tr[3];
                ldsm4t(tr, bL + off);
                Bl[2*p][0] = tr[0]; Bl[2*p][1] = tr[1];
                Bl[2*p+1][0] = tr[2]; Bl[2*p+1][1] = tr[3];
            }
            #pragma unroll
            for (int s = 0; s < 4; s++)
                #pragma unroll
                for (int n = 0; n < 4; n++) {
                    mma_bf16(acc[s][n], Ah[s], Bh[n]);
                    mma_bf16(acc[s][n], Ah[s], Bl[n]);
                    mma_bf16(acc[s][n], Al[s], Bh[n]);
                }
        }
        __syncthreads();
    }

    #pragma unroll
    for (int s = 0; s < 4; s++) {
        int r0 = rowBase + wm * 64 + s * 16 + (lane >> 2);
        #pragma unroll
        for (int n = 0; n < 4; n++) {
            int c0 = wn * 32 + n * 8 + ((lane & 3) << 1);
            uint32_t h0, l0, h1, l1;
            split2(acc[s][n][0], acc[s][n][1], h0, l0);
            split2(acc[s][n][2], acc[s][n][3], h1, l1);
            *(uint32_t*)&Czh[(size_t)r0 * D_ + c0]       = h0;
            *(uint32_t*)&Czl[(size_t)r0 * D_ + c0]       = l0;
            *(uint32_t*)&Czh[(size_t)(r0 + 8) * D_ + c0] = h1;
            *(uint32_t*)&Czl[(size_t)(r0 + 8) * D_ + c0] = l1;
        }
    }
}

// ---------------- RoPE tables -----------------------------------------------------
__global__ void rope_tables()
{
    int i = blockIdx.x * blockDim.x + threadIdx.x;
    if (i >= S_ * 64) return;
    int d = i & 63;
    int s = i >> 6;
    double inv = pow(10000.0, -(double)d / 64.0);
    double ang = (double)s * inv;
    g_cos[i] = (float)cos(ang);
    g_sin[i] = (float)sin(ang);
}

// ---------------- RoPE apply: fp32 Q/K -> split bf16 (scale folded into Q) -------
__global__ void rope_apply()
{
    size_t i = (size_t)blockIdx.x * blockDim.x + threadIdx.x;
    if (i >= (size_t)M_ * H_ * 64) return;
    int d = (int)(i & 63);
    int h = (int)((i >> 6) & (H_ - 1));
    int m = (int)(i >> 10);
    int s = m & (S_ - 1);
    float c  = g_cos[s * 64 + d];
    float sn = g_sin[s * 64 + d];
    const float scale = 0.08838834764831845f;   // 1/sqrt(128)
    size_t base = (size_t)m * D_ + h * HD_ + d;

    float q1 = g_Q[base], q2 = g_Q[base + 64];
    float qr1 = (q1 * c - q2 * sn) * scale;
    float qr2 = (q2 * c + q1 * sn) * scale;
    __nv_bfloat16 qh1 = __float2bfloat16(qr1);
    __nv_bfloat16 qh2 = __float2bfloat16(qr2);
    g_Qh[base]      = qh1; g_Ql[base]      = __float2bfloat16(qr1 - __bfloat162float(qh1));
    g_Qh[base + 64] = qh2; g_Ql[base + 64] = __float2bfloat16(qr2 - __bfloat162float(qh2));

    float k1 = g_K[base], k2 = g_K[base + 64];
    float kr1 = k1 * c - k2 * sn;
    float kr2 = k2 * c + k1 * sn;
    __nv_bfloat16 kh1 = __float2bfloat16(kr1);
    __nv_bfloat16 kh2 = __float2bfloat16(kr2);
    g_Kh[base]      = kh1; g_Kl[base]      = __float2bfloat16(kr1 - __bfloat162float(kh1));
    g_Kh[base + 64] = kh2; g_Kl[base + 64] = __float2bfloat16(kr2 - __bfloat162float(kh2));
}

// ---------------- causal softmax: fp32 scores -> split bf16 probs (zero-padded) ---
__global__ void softmax_rows()
{
    int gw   = (blockIdx.x * blockDim.x + threadIdx.x) >> 5;
    int lane = threadIdx.x & 31;
    if (gw >= B_ * H_ * S_) return;
    int s  = gw & (S_ - 1);
    int bh = gw >> 11;
    const float* row = g_P + (size_t)bh * S_ * S_ + (size_t)s * S_;
    __nv_bfloat16* oh = g_Ph + (size_t)bh * S_ * S_ + (size_t)s * S_;
    __nv_bfloat16* ol = g_Pl + (size_t)bh * S_ * S_ + (size_t)s * S_;
    int n = s + 1;
    int padEnd = ((s >> 7) + 1) << 7;            // next 128 boundary

    float mx = -3.4e38f;
    for (int j = lane; j < n; j += 32) mx = fmaxf(mx, row[j]);
    #pragma unroll
    for (int o = 16; o; o >>= 1) mx = fmaxf(mx, __shfl_xor_sync(0xffffffffu, mx, o));

    float sum = 0.f;
    for (int j = lane; j < n; j += 32) sum += __expf(row[j] - mx);
    #pragma unroll
    for (int o = 16; o; o >>= 1) sum += __shfl_xor_sync(0xffffffffu, sum, o);

    float inv = 1.f / sum;
    for (int j = lane; j < padEnd; j += 32) {
        float p = (j < n) ? __expf(row[j] - mx) * inv : 0.f;
        __nv_bfloat16 ph = __float2bfloat16(p);
        oh[j] = ph;
        ol[j] = __float2bfloat16(p - __bfloat162float(ph));
    }
}

// ---------------- launch ----------------------------------------------------------
extern "C" void kernel_launch(void* const* d_in, const int* in_sizes, int n_in,
                              void* d_out, int out_size)
{
    const float* x  = (const float*)d_in[0];
    const float* Wq = (const float*)d_in[1];
    const float* Wk = (const float*)d_in[2];
    const float* Wv = (const float*)d_in[3];
    const float* Wo = (const float*)d_in[4];
    float* out = (float*)d_out;

    float *Qp, *Kp, *Pp;
    cudaGetSymbolAddress((void**)&Qp, g_Q);
    cudaGetSymbolAddress((void**)&Kp, g_K);
    cudaGetSymbolAddress((void**)&Pp, g_P);
    __nv_bfloat16 *xh, *xl, *Wqh, *Wql, *Wkh, *Wkl, *Wvh, *Wvl, *Woh, *Wol;
    __nv_bfloat16 *Qh, *Ql, *Kh, *Kl, *Vh, *Vl, *AOh, *AOl;
    cudaGetSymbolAddress((void**)&xh,  g_xh);  cudaGetSymbolAddress((void**)&xl,  g_xl);
    cudaGetSymbolAddress((void**)&Wqh, g_Wqh); cudaGetSymbolAddress((void**)&Wql, g_Wql);
    cudaGetSymbolAddress((void**)&Wkh, g_Wkh); cudaGetSymbolAddress((void**)&Wkl, g_Wkl);
    cudaGetSymbolAddress((void**)&Wvh, g_Wvh); cudaGetSymbolAddress((void**)&Wvl, g_Wvl);
    cudaGetSymbolAddress((void**)&Woh, g_Woh); cudaGetSymbolAddress((void**)&Wol, g_Wol);
    cudaGetSymbolAddress((void**)&Qh,  g_Qh);  cudaGetSymbolAddress((void**)&Ql,  g_Ql);
    cudaGetSymbolAddress((void**)&Kh,  g_Kh);  cudaGetSymbolAddress((void**)&Kl,  g_Kl);
    cudaGetSymbolAddress((void**)&Vh,  g_Vh);  cudaGetSymbolAddress((void**)&Vl,  g_Vl);
    cudaGetSymbolAddress((void**)&AOh, g_AOh); cudaGetSymbolAddress((void**)&AOl, g_AOl);

    cudaFuncSetAttribute(gemm_bs, cudaFuncAttributeMaxDynamicSharedMemorySize, 131072);
    cudaFuncSetAttribute(gemm_pv, cudaFuncAttributeMaxDynamicSharedMemorySize, 131072);

    dim3 blk(256);

    // 0) split inputs
    {
        int n4x = (int)((size_t)M_ * D_ / 4);
        int n4w = (int)((size_t)D_ * D_ / 4);
        split_arr<<<(n4x + 255) / 256, blk>>>((const float4*)x,  (uint2*)xh,  (uint2*)xl,  n4x);
        split_arr<<<(n4w + 255) / 256, blk>>>((const float4*)Wq, (uint2*)Wqh, (uint2*)Wql, n4w);
        split_arr<<<(n4w + 255) / 256, blk>>>((const float4*)Wk, (uint2*)Wkh, (uint2*)Wkl, n4w);
        split_arr<<<(n4w + 255) / 256, blk>>>((const float4*)Wv, (uint2*)Wvh, (uint2*)Wvl, n4w);
        split_arr<<<(n4w + 255) / 256, blk>>>((const float4*)Wo, (uint2*)Woh, (uint2*)Wol, n4w);
    }

    // 1) projections: Q,K fp32 (rope follows) ; V split direct
    dim3 gProj(D_ / 128, M_ / 128, 1);
    gemm_bs<<<gProj, blk, 131072>>>(xh, xl, Wqh, Wql, Qp, 0, 0,
                                    D_, D_, D_, D_, 1, 0,0,0,0,0,0, 0, 0);
    gemm_bs<<<gProj, blk, 131072>>>(xh, xl, Wkh, Wkl, Kp, 0, 0,
                                    D_, D_, D_, D_, 1, 0,0,0,0,0,0, 0, 0);
    gemm_bs<<<gProj, blk, 131072>>>(xh, xl, Wvh, Wvl, 0, Vh, Vl,
                                    D_, D_, D_, D_, 1, 0,0,0,0,0,0, 0, 1);

    // 2) RoPE (writes split Q/K, scale folded into Q)
    rope_tables<<<(S_ * 64 + 255) / 256, blk>>>();
    rope_apply<<<((size_t)M_ * H_ * 64 + 255) / 256, blk>>>();

    // 3) scores = Q K^T per (b,h), causal block skip, fp32 out
    dim3 gScore(S_ / 128, S_ / 128, B_ * H_);
    gemm_bs<<<gScore, blk, 131072>>>(Qh, Ql, Kh, Kl, Pp, 0, 0,
                                     HD_, D_, D_, S_,
                                     H_,
                                     (long long)S_ * D_, (long long)HD_,
                                     (long long)S_ * D_, (long long)HD_,
                                     (long long)H_ * S_ * S_, (long long)S_ * S_,
                                     1, 0);

    // 4) softmax -> split bf16 probs, zero-padded to 128 boundary
    {
        long long warps = (long long)B_ * H_ * S_;
        long long threads = warps * 32;
        softmax_rows<<<(unsigned)((threads + 255) / 256), blk>>>();
    }

    // 5) attn_out = P * V -> split bf16
    dim3 gPV(1, S_ / 128, B_ * H_);
    gemm_pv<<<gPV, blk, 131072>>>();

    // 6) out = AO * Wo^T, fp32 out
    gemm_bs<<<gProj, blk, 131072>>>(AOh, AOl, Woh, Wol, out, 0, 0,
                                    D_, D_, D_, D_, 1, 0,0,0,0,0,0, 0, 0);
}

// round 9
// speedup vs baseline: 3.4134x; 1.0004x over previous
#include <cuda_runtime.h>
#include <cuda_bf16.h>
#include <math.h>
#include <stdint.h>

#define B_  2
#define S_  2048
#define D_  2048
#define H_  16
#define HD_ 128
#define M_  (B_*S_)      // 4096 rows total

// ---------------- scratch (device globals; no allocation allowed) ----------------
__device__ float g_Q[(size_t)M_*D_];                 // fp32 proj out (pre-rope)
__device__ float g_K[(size_t)M_*D_];
__device__ float g_P[(size_t)B_*H_*S_*S_];           // fp32 scores
__device__ float g_cos[S_*64];
__device__ float g_sin[S_*64];

__device__ __nv_bfloat16 g_xh[(size_t)M_*D_],  g_xl[(size_t)M_*D_];
__device__ __nv_bfloat16 g_Wqh[(size_t)D_*D_], g_Wql[(size_t)D_*D_];
__device__ __nv_bfloat16 g_Wkh[(size_t)D_*D_], g_Wkl[(size_t)D_*D_];
__device__ __nv_bfloat16 g_Wvh[(size_t)D_*D_], g_Wvl[(size_t)D_*D_];
__device__ __nv_bfloat16 g_Woh[(size_t)D_*D_], g_Wol[(size_t)D_*D_];
__device__ __nv_bfloat16 g_Qh[(size_t)M_*D_],  g_Ql[(size_t)M_*D_];
__device__ __nv_bfloat16 g_Kh[(size_t)M_*D_],  g_Kl[(size_t)M_*D_];
__device__ __nv_bfloat16 g_Vh[(size_t)M_*D_],  g_Vl[(size_t)M_*D_];
__device__ __nv_bfloat16 g_Ph[(size_t)B_*H_*S_*S_], g_Pl[(size_t)B_*H_*S_*S_];
__device__ __nv_bfloat16 g_AOh[(size_t)M_*D_], g_AOl[(size_t)M_*D_];

// ---------------- helpers ---------------------------------------------------------
__device__ __forceinline__ uint32_t smem_u32(const void* p) {
    return (uint32_t)__cvta_generic_to_shared(p);
}
__device__ __forceinline__ void cpa16(uint32_t dst, const void* src) {
    asm volatile("cp.async.cg.shared.global [%0],[%1],16;" :: "r"(dst), "l"(src));
}
__device__ __forceinline__ void cpa_commit() { asm volatile("cp.async.commit_group;"); }
template<int N> __device__ __forceinline__ void cpa_wait() {
    asm volatile("cp.async.wait_group %0;" :: "n"(N));
}
__device__ __forceinline__ void ldsm4(uint32_t r[4], uint32_t addr) {
    asm volatile("ldmatrix.sync.aligned.m8n8.x4.shared.b16 {%0,%1,%2,%3},[%4];"
                 : "=r"(r[0]), "=r"(r[1]), "=r"(r[2]), "=r"(r[3]) : "r"(addr));
}
__device__ __forceinline__ void ldsm4t(uint32_t r[4], uint32_t addr) {
    asm volatile("ldmatrix.sync.aligned.m8n8.x4.trans.shared.b16 {%0,%1,%2,%3},[%4];"
                 : "=r"(r[0]), "=r"(r[1]), "=r"(r[2]), "=r"(r[3]) : "r"(addr));
}
__device__ __forceinline__ void mma_bf16(float d[4], const uint32_t a[4], const uint32_t b[2]) {
    asm volatile(
        "mma.sync.aligned.m16n8k16.row.col.f32.bf16.bf16.f32 "
        "{%0,%1,%2,%3},{%4,%5,%6,%7},{%8,%9},{%0,%1,%2,%3};"
        : "+f"(d[0]), "+f"(d[1]), "+f"(d[2]), "+f"(d[3])
        : "r"(a[0]), "r"(a[1]), "r"(a[2]), "r"(a[3]), "r"(b[0]), "r"(b[1]));
}
__device__ __forceinline__ void split2(float x0, float x1, uint32_t &h, uint32_t &l) {
    __nv_bfloat16 h0 = __float2bfloat16(x0);
    __nv_bfloat16 h1 = __float2bfloat16(x1);
    __nv_bfloat16 l0 = __float2bfloat16(x0 - __bfloat162float(h0));
    __nv_bfloat16 l1 = __float2bfloat16(x1 - __bfloat162float(h1));
    __nv_bfloat162 hp = __halves2bfloat162(h0, h1);
    __nv_bfloat162 lp = __halves2bfloat162(l0, l1);
    h = *reinterpret_cast<uint32_t*>(&hp);
    l = *reinterpret_cast<uint32_t*>(&lp);
}

// ---------------- elementwise fp32 -> (hi,lo) convert -----------------------------
__global__ __launch_bounds__(256)
void split_arr(const float4* __restrict__ src,
               uint2* __restrict__ h, uint2* __restrict__ l, int n4)
{
    int i = blockIdx.x * blockDim.x + threadIdx.x;
    if (i >= n4) return;
    float4 v = src[i];
    uint32_t h0, l0, h1, l1;
    split2(v.x, v.y, h0, l0);
    split2(v.z, v.w, h1, l1);
    h[i] = make_uint2(h0, h1);
    l[i] = make_uint2(l0, l1);
}

// ============================================================================
// C = A * B^T, pre-split bf16 planar hi/lo. CTA 128x128, k-tile 64,
// double-buffered cp.async. 512 threads, 16 warps (4m x 4n), warp 32x32.
// smem: 2 stages x { Ah 16K | Al 16K | Bh 16K | Bl 16K } = 128KB.
// outSplit: 0 -> C fp32 ; 1 -> Ch/Cl bf16.
// ============================================================================
__global__ __launch_bounds__(512)
void gemm_bs(const __nv_bfloat16* __restrict__ Agh, const __nv_bfloat16* __restrict__ Agl,
             const __nv_bfloat16* __restrict__ Bgh, const __nv_bfloat16* __restrict__ Bgl,
             float* __restrict__ C,
             __nv_bfloat16* __restrict__ Ch, __nv_bfloat16* __restrict__ Cl,
             int K, int lda, int ldb, int ldc,
             int zdiv,
             long long sAo, long long sAi,
             long long sBo, long long sBi,
             long long sCo, long long sCi,
             int causalSkip, int outSplit)
{
    int z = blockIdx.z;
    int zo = z / zdiv, zi = z - zo * zdiv;
    long long aOff = zo * sAo + zi * sAi;
    long long bOff = zo * sBo + zi * sBi;
    long long cOff = zo * sCo + zi * sCi;
    Agh += aOff; Agl += aOff;
    Bgh += bOff; Bgl += bOff;

    int rowBase = blockIdx.y * 128;
    int colBase = blockIdx.x * 128;
    if (causalSkip && colBase > rowBase) return;

    extern __shared__ __align__(16) char sraw[];
    uint32_t sb = smem_u32(sraw);

    int tid = threadIdx.x, lane = tid & 31, w = tid >> 5;
    int wm = w >> 2, wn = w & 3;
    int lr = lane & 7, grp = lane >> 3;

    int agk = grp >> 1;
    uint32_t arow[2], arx[2];
    #pragma unroll
    for (int s = 0; s < 2; s++) {
        int r = wm * 32 + s * 16 + ((grp & 1) << 3) + lr;
        arow[s] = (uint32_t)r << 7;
        arx[s]  = r & 7;
    }
    int bgk = grp & 1;
    uint32_t brow[2], brx[2];
    #pragma unroll
    for (int p = 0; p < 2; p++) {
        int r = wn * 32 + p * 16 + ((grp >> 1) << 3) + lr;
        brow[p] = (uint32_t)r << 7;
        brx[p]  = r & 7;
    }

    float acc[2][4][4];
    #pragma unroll
    for (int s = 0; s < 2; s++)
        #pragma unroll
        for (int n = 0; n < 4; n++)
            #pragma unroll
            for (int j = 0; j < 4; j++) acc[s][n][j] = 0.f;

    int T = K >> 6;

    auto issue = [&](int t, int stg) {
        uint32_t base = sb + (uint32_t)stg * 65536u;
        int k0 = t << 6;
        #pragma unroll
        for (int i = 0; i < 2; i++) {
            int id = tid + (i << 9);
            int r = id >> 3, c = id & 7;
            uint32_t dst = base + ((uint32_t)r << 7) + (uint32_t)((c ^ (r & 7)) << 4);
            cpa16(dst,           Agh + (size_t)(rowBase + r) * lda + k0 + (c << 3));
            cpa16(dst + 16384u,  Agl + (size_t)(rowBase + r) * lda + k0 + (c << 3));
        }
        #pragma unroll
        for (int i = 0; i < 2; i++) {
            int id = tid + (i << 9);
            int r = id >> 3, c = id & 7;
            uint32_t dst = base + 32768u + ((uint32_t)r << 7) + (uint32_t)((c ^ (r & 7)) << 4);
            cpa16(dst,           Bgh + (size_t)(colBase + r) * ldb + k0 + (c << 3));
            cpa16(dst + 16384u,  Bgl + (size_t)(colBase + r) * ldb + k0 + (c << 3));
        }
        cpa_commit();
    };

    issue(0, 0);
    for (int t = 0; t < T; t++) {
        int stg = t & 1;
        if (t + 1 < T) { issue(t + 1, stg ^ 1); cpa_wait<1>(); }
        else          { cpa_wait<0>(); }
        __syncthreads();

        uint32_t aH = sb + (uint32_t)stg * 65536u;
        uint32_t aL = aH + 16384u;
        uint32_t bH = aH + 32768u;
        uint32_t bL = aH + 49152u;

        #pragma unroll
        for (int st = 0; st < 4; st++) {
            uint32_t Ah[2][4], Al[2][4], Bh[4][2], Bl[4][2];
            #pragma unroll
            for (int s = 0; s < 2; s++) {
                uint32_t off = arow[s] + ((((st << 1) + agk) ^ arx[s]) << 4);
                ldsm4(Ah[s], aH + off);
                ldsm4(Al[s], aL + off);
            }
            #pragma unroll
            for (int p = 0; p < 2; p++) {
                uint32_t off = brow[p] + ((((st << 1) + bgk) ^ brx[p]) << 4);
                uint32_t tr[4];
                ldsm4(tr, bH + off);
                Bh[2*p][0] = tr[0]; Bh[2*p][1] = tr[1];
                Bh[2*p+1][0] = tr[2]; Bh[2*p+1][1] = tr[3];
                ldsm4(tr, bL + off);
                Bl[2*p][0] = tr[0]; Bl[2*p][1] = tr[1];
                Bl[2*p+1][0] = tr[2]; Bl[2*p+1][1] = tr[3];
            }
            #pragma unroll
            for (int s = 0; s < 2; s++)
                #pragma unroll
                for (int n = 0; n < 4; n++) {
                    mma_bf16(acc[s][n], Ah[s], Bh[n]);
                    mma_bf16(acc[s][n], Ah[s], Bl[n]);
                    mma_bf16(acc[s][n], Al[s], Bh[n]);
                }
        }
        __syncthreads();
    }

    // ---- epilogue ----
    #pragma unroll
    for (int s = 0; s < 2; s++) {
        int r0 = rowBase + wm * 32 + s * 16 + (lane >> 2);
        #pragma unroll
        for (int n = 0; n < 4; n++) {
            int c0 = colBase + wn * 32 + n * 8 + ((lane & 3) << 1);
            if (!outSplit) {
                float* Cb = C + cOff;
                *(float2*)&Cb[(size_t)r0 * ldc + c0]       = make_float2(acc[s][n][0], acc[s][n][1]);
                *(float2*)&Cb[(size_t)(r0 + 8) * ldc + c0] = make_float2(acc[s][n][2], acc[s][n][3]);
            } else {
                __nv_bfloat16* Hb = Ch + cOff;
                __nv_bfloat16* Lb = Cl + cOff;
                uint32_t h0, l0, h1, l1;
                split2(acc[s][n][0], acc[s][n][1], h0, l0);
                split2(acc[s][n][2], acc[s][n][3], h1, l1);
                *(uint32_t*)&Hb[(size_t)r0 * ldc + c0]       = h0;
                *(uint32_t*)&Lb[(size_t)r0 * ldc + c0]       = l0;
                *(uint32_t*)&Hb[(size_t)(r0 + 8) * ldc + c0] = h1;
                *(uint32_t*)&Lb[(size_t)(r0 + 8) * ldc + c0] = l1;
            }
        }
    }
}

// ============================================================================
// AO = P * V : P pre-split (zero-padded causal), V pre-split [k][n].
// 512 threads, 16 warps (4x4), warp 32x32. k loop truncated at rowBase+128.
// ============================================================================
__global__ __launch_bounds__(512)
void gemm_pv()
{
    int z = blockIdx.z;
    int b = z >> 4, h = z & 15;
    const __nv_bfloat16* __restrict__ Pzh = g_Ph + (size_t)z * S_ * S_;
    const __nv_bfloat16* __restrict__ Pzl = g_Pl + (size_t)z * S_ * S_;
    const __nv_bfloat16* __restrict__ Vzh = g_Vh + (size_t)b * S_ * D_ + h * HD_;
    const __nv_bfloat16* __restrict__ Vzl = g_Vl + (size_t)b * S_ * D_ + h * HD_;
    __nv_bfloat16* __restrict__ Czh = g_AOh + (size_t)b * S_ * D_ + h * HD_;
    __nv_bfloat16* __restrict__ Czl = g_AOl + (size_t)b * S_ * D_ + h * HD_;

    int rowBase = blockIdx.y * 128;

    extern __shared__ __align__(16) char sraw[];
    uint32_t sb = smem_u32(sraw);

    int tid = threadIdx.x, lane = tid & 31, w = tid >> 5;
    int wm = w >> 2, wn = w & 3;
    int lr = lane & 7, grp = lane >> 3;

    int agk = grp >> 1;
    uint32_t arow[2], arx[2];
    #pragma unroll
    for (int s = 0; s < 2; s++) {
        int r = wm * 32 + s * 16 + ((grp & 1) << 3) + lr;
        arow[s] = (uint32_t)r << 7;
        arx[s]  = r & 7;
    }
    int krb = ((grp & 1) << 3) + lr;
    uint32_t bvoff[2];
    #pragma unroll
    for (int p = 0; p < 2; p++) {
        int nc = wn * 4 + p * 2 + (grp >> 1);
        bvoff[p] = ((uint32_t)krb << 8) + (uint32_t)((nc ^ (krb & 7)) << 4);
    }

    float acc[2][4][4];
    #pragma unroll
    for (int s = 0; s < 2; s++)
        #pragma unroll
        for (int n = 0; n < 4; n++)
            #pragma unroll
            for (int j = 0; j < 4; j++) acc[s][n][j] = 0.f;

    int T = (rowBase >> 6) + 2;

    auto issue = [&](int t, int stg) {
        uint32_t base = sb + (uint32_t)stg * 65536u;
        int k0 = t << 6;
        #pragma unroll
        for (int i = 0; i < 2; i++) {
            int id = tid + (i << 9);
            int r = id >> 3, c = id & 7;
            uint32_t dst = base + ((uint32_t)r << 7) + (uint32_t)((c ^ (r & 7)) << 4);
            cpa16(dst,           Pzh + (size_t)(rowBase + r) * S_ + k0 + (c << 3));
            cpa16(dst + 16384u,  Pzl + (size_t)(rowBase + r) * S_ + k0 + (c << 3));
        }
        #pragma unroll
        for (int i = 0; i < 2; i++) {
            int id = tid + (i << 9);
            int kr = id >> 4, c = id & 15;
            uint32_t dst = base + 32768u + ((uint32_t)kr << 8) + (uint32_t)((c ^ (kr & 7)) << 4);
            cpa16(dst,           Vzh + (size_t)(k0 + kr) * D_ + (c << 3));
            cpa16(dst + 16384u,  Vzl + (size_t)(k0 + kr) * D_ + (c << 3));
        }
        cpa_commit();
    };

    issue(0, 0);
    for (int t = 0; t < T; t++) {
        int stg = t & 1;
        if (t + 1 < T) { issue(t + 1, stg ^ 1); cpa_wait<1>(); }
        else          { cpa_wait<0>(); }
        __syncthreads();

        uint32_t aH = sb + (uint32_t)stg * 65536u;
        uint32_t aL = aH + 16384u;
        uint32_t bH = aH + 32768u;
        uint32_t bL = aH + 49152u;

        #pragma unroll
        for (int st = 0; st < 4; st++) {
            uint32_t Ah[2][4], Al[2][4], Bh[4][2], Bl[4][2];
            #pragma unroll
            for (int s = 0; s < 2; s++) {
                uint32_t off = arow[s] + ((((st << 1) + agk) ^ arx[s]) << 4);
                ldsm4(Ah[s], aH + off);
                ldsm4(Al[s], aL + off);
            }
            #pragma unroll
            for (int p = 0; p < 2; p++) {
                uint32_t off = ((uint32_t)st << 12) + bvoff[p];
                uint32_t tr[4];
                ldsm4t(tr, bH + off);
                Bh[2*p][0] = tr[0]; Bh[2*p][1] = tr[1];
                Bh[2*p+1][0] = tr[2]; Bh[2*p+1][1] = tr[3];
                ldsm4t(tr, bL + off);
                Bl[2*p][0] = tr[0]; Bl[2*p][1] = tr[1];
                Bl[2*p+1][0] = tr[2]; Bl[2*p+1][1] = tr[3];
            }
            #pragma unroll
            for (int s = 0; s < 2; s++)
                #pragma unroll
                for (int n = 0; n < 4; n++) {
                    mma_bf16(acc[s][n], Ah[s], Bh[n]);
                    mma_bf16(acc[s][n], Ah[s], Bl[n]);
                    mma_bf16(acc[s][n], Al[s], Bh[n]);
                }
        }
        __syncthreads();
    }

    #pragma unroll
    for (int s = 0; s < 2; s++) {
        int r0 = rowBase + wm * 32 + s * 16 + (lane >> 2);
        #pragma unroll
        for (int n = 0; n < 4; n++) {
            int c0 = wn * 32 + n * 8 + ((lane & 3) << 1);
            uint32_t h0, l0, h1, l1;
            split2(acc[s][n][0], acc[s][n][1], h0, l0);
            split2(acc[s][n][2], acc[s][n][3], h1, l1);
            *(uint32_t*)&Czh[(size_t)r0 * D_ + c0]       = h0;
            *(uint32_t*)&Czl[(size_t)r0 * D_ + c0]       = l0;
            *(uint32_t*)&Czh[(size_t)(r0 + 8) * D_ + c0] = h1;
            *(uint32_t*)&Czl[(size_t)(r0 + 8) * D_ + c0] = l1;
        }
    }
}

// ---------------- RoPE tables -----------------------------------------------------
__global__ void rope_tables()
{
    int i = blockIdx.x * blockDim.x + threadIdx.x;
    if (i >= S_ * 64) return;
    int d = i & 63;
    int s = i >> 6;
    double inv = exp2(-(double)d / 64.0 * 13.287712379549449);   // log2(10000)
    double ang = (double)s * inv;
    g_cos[i] = (float)cos(ang);
    g_sin[i] = (float)sin(ang);
}

// ---------------- RoPE apply: fp32 Q/K -> split bf16 (scale folded into Q) -------
__global__ void rope_apply()
{
    size_t i = (size_t)blockIdx.x * blockDim.x + threadIdx.x;
    if (i >= (size_t)M_ * H_ * 64) return;
    int d = (int)(i & 63);
    int h = (int)((i >> 6) & (H_ - 1));
    int m = (int)(i >> 10);
    int s = m & (S_ - 1);
    float c  = g_cos[s * 64 + d];
    float sn = g_sin[s * 64 + d];
    const float scale = 0.08838834764831845f;   // 1/sqrt(128)
    size_t base = (size_t)m * D_ + h * HD_ + d;

    float q1 = g_Q[base], q2 = g_Q[base + 64];
    float qr1 = (q1 * c - q2 * sn) * scale;
    float qr2 = (q2 * c + q1 * sn) * scale;
    __nv_bfloat16 qh1 = __float2bfloat16(qr1);
    __nv_bfloat16 qh2 = __float2bfloat16(qr2);
    g_Qh[base]      = qh1; g_Ql[base]      = __float2bfloat16(qr1 - __bfloat162float(qh1));
    g_Qh[base + 64] = qh2; g_Ql[base + 64] = __float2bfloat16(qr2 - __bfloat162float(qh2));

    float k1 = g_K[base], k2 = g_K[base + 64];
    float kr1 = k1 * c - k2 * sn;
    float kr2 = k2 * c + k1 * sn;
    __nv_bfloat16 kh1 = __float2bfloat16(kr1);
    __nv_bfloat16 kh2 = __float2bfloat16(kr2);
    g_Kh[base]      = kh1; g_Kl[base]      = __float2bfloat16(kr1 - __bfloat162float(kh1));
    g_Kh[base + 64] = kh2; g_Kl[base + 64] = __float2bfloat16(kr2 - __bfloat162float(kh2));
}

// ---------------- causal softmax: fp32 scores -> split bf16 probs (zero-padded) ---
__global__ void softmax_rows()
{
    int gw   = (blockIdx.x * blockDim.x + threadIdx.x) >> 5;
    int lane = threadIdx.x & 31;
    if (gw >= B_ * H_ * S_) return;
    int s  = gw & (S_ - 1);
    int bh = gw >> 11;
    const float* row = g_P + (size_t)bh * S_ * S_ + (size_t)s * S_;
    __nv_bfloat16* oh = g_Ph + (size_t)bh * S_ * S_ + (size_t)s * S_;
    __nv_bfloat16* ol = g_Pl + (size_t)bh * S_ * S_ + (size_t)s * S_;
    int n = s + 1;
    int padEnd = ((s >> 7) + 1) << 7;

    float mx = -3.4e38f;
    for (int j = lane; j < n; j += 32) mx = fmaxf(mx, row[j]);
    #pragma unroll
    for (int o = 16; o; o >>= 1) mx = fmaxf(mx, __shfl_xor_sync(0xffffffffu, mx, o));

    float sum = 0.f;
    for (int j = lane; j < n; j += 32) sum += __expf(row[j] - mx);
    #pragma unroll
    for (int o = 16; o; o >>= 1) sum += __shfl_xor_sync(0xffffffffu, sum, o);

    float inv = 1.f / sum;
    for (int j = lane; j < padEnd; j += 32) {
        float p = (j < n) ? __expf(row[j] - mx) * inv : 0.f;
        __nv_bfloat16 ph = __float2bfloat16(p);
        oh[j] = ph;
        ol[j] = __float2bfloat16(p - __bfloat162float(ph));
    }
}

// ---------------- launch ----------------------------------------------------------
extern "C" void kernel_launch(void* const* d_in, const int* in_sizes, int n_in,
                              void* d_out, int out_size)
{
    const float* x  = (const float*)d_in[0];
    const float* Wq = (const float*)d_in[1];
    const float* Wk = (const float*)d_in[2];
    const float* Wv = (const float*)d_in[3];
    const float* Wo = (const float*)d_in[4];
    float* out = (float*)d_out;

    float *Qp, *Kp, *Pp;
    cudaGetSymbolAddress((void**)&Qp, g_Q);
    cudaGetSymbolAddress((void**)&Kp, g_K);
    cudaGetSymbolAddress((void**)&Pp, g_P);
    __nv_bfloat16 *xh, *xl, *Wqh, *Wql, *Wkh, *Wkl, *Wvh, *Wvl, *Woh, *Wol;
    __nv_bfloat16 *Qh, *Ql, *Kh, *Kl, *Vh, *Vl, *AOh, *AOl;
    cudaGetSymbolAddress((void**)&xh,  g_xh);  cudaGetSymbolAddress((void**)&xl,  g_xl);
    cudaGetSymbolAddress((void**)&Wqh, g_Wqh); cudaGetSymbolAddress((void**)&Wql, g_Wql);
    cudaGetSymbolAddress((void**)&Wkh, g_Wkh); cudaGetSymbolAddress((void**)&Wkl, g_Wkl);
    cudaGetSymbolAddress((void**)&Wvh, g_Wvh); cudaGetSymbolAddress((void**)&Wvl, g_Wvl);
    cudaGetSymbolAddress((void**)&Woh, g_Woh); cudaGetSymbolAddress((void**)&Wol, g_Wol);
    cudaGetSymbolAddress((void**)&Qh,  g_Qh);  cudaGetSymbolAddress((void**)&Ql,  g_Ql);
    cudaGetSymbolAddress((void**)&Kh,  g_Kh);  cudaGetSymbolAddress((void**)&Kl,  g_Kl);
    cudaGetSymbolAddress((void**)&Vh,  g_Vh);  cudaGetSymbolAddress((void**)&Vl,  g_Vl);
    cudaGetSymbolAddress((void**)&AOh, g_AOh); cudaGetSymbolAddress((void**)&AOl, g_AOl);

    cudaFuncSetAttribute(gemm_bs, cudaFuncAttributeMaxDynamicSharedMemorySize, 131072);
    cudaFuncSetAttribute(gemm_pv, cudaFuncAttributeMaxDynamicSharedMemorySize, 131072);

    dim3 blk256(256), blk512(512);

    // 0) split inputs
    {
        int n4x = (int)((size_t)M_ * D_ / 4);
        int n4w = (int)((size_t)D_ * D_ / 4);
        split_arr<<<(n4x + 255) / 256, blk256>>>((const float4*)x,  (uint2*)xh,  (uint2*)xl,  n4x);
        split_arr<<<(n4w + 255) / 256, blk256>>>((const float4*)Wq, (uint2*)Wqh, (uint2*)Wql, n4w);
        split_arr<<<(n4w + 255) / 256, blk256>>>((const float4*)Wk, (uint2*)Wkh, (uint2*)Wkl, n4w);
        split_arr<<<(n4w + 255) / 256, blk256>>>((const float4*)Wv, (uint2*)Wvh, (uint2*)Wvl, n4w);
        split_arr<<<(n4w + 255) / 256, blk256>>>((const float4*)Wo, (uint2*)Woh, (uint2*)Wol, n4w);
    }

    // 1) projections: Q,K fp32 (rope follows) ; V split direct
    dim3 gProj(D_ / 128, M_ / 128, 1);
    gemm_bs<<<gProj, blk512, 131072>>>(xh, xl, Wqh, Wql, Qp, 0, 0,
                                       D_, D_, D_, D_, 1, 0,0,0,0,0,0, 0, 0);
    gemm_bs<<<gProj, blk512, 131072>>>(xh, xl, Wkh, Wkl, Kp, 0, 0,
                                       D_, D_, D_, D_, 1, 0,0,0,0,0,0, 0, 0);
    gemm_bs<<<gProj, blk512, 131072>>>(xh, xl, Wvh, Wvl, 0, Vh, Vl,
                                       D_, D_, D_, D_, 1, 0,0,0,0,0,0, 0, 1);

    // 2) RoPE
    rope_tables<<<(S_ * 64 + 255) / 256, blk256>>>();
    rope_apply<<<((size_t)M_ * H_ * 64 + 255) / 256, blk256>>>();

    // 3) scores = Q K^T per (b,h), causal block skip, fp32 out
    dim3 gScore(S_ / 128, S_ / 128, B_ * H_);
    gemm_bs<<<gScore, blk512, 131072>>>(Qh, Ql, Kh, Kl, Pp, 0, 0,
                                        HD_, D_, D_, S_,
                                        H_,
                                        (long long)S_ * D_, (long long)HD_,
                                        (long long)S_ * D_, (long long)HD_,
                                        (long long)H_ * S_ * S_, (long long)S_ * S_,
                                        1, 0);

    // 4) softmax -> split bf16 probs, zero-padded to 128 boundary
    {
        long long warps = (long long)B_ * H_ * S_;
        long long threads = warps * 32;
        softmax_rows<<<(unsigned)((threads + 255) / 256), blk256>>>();
    }

    // 5) attn_out = P * V -> split bf16
    dim3 gPV(1, S_ / 128, B_ * H_);
    gemm_pv<<<gPV, blk512, 131072>>>();

    // 6) out = AO * Wo^T, fp32 out
    gemm_bs<<<gProj, blk512, 131072>>>(AOh, AOl, Woh, Wol, out, 0, 0,
                                       D_, D_, D_, D_, 1, 0,0,0,0,0,0, 0, 0);
}

// round 10
// speedup vs baseline: 3.5557x; 1.0417x over previous
#include <cuda_runtime.h>
#include <cuda_bf16.h>
#include <math.h>
#include <stdint.h>

#define B_  2
#define S_  2048
#define D_  2048
#define H_  16
#define HD_ 128
#define M_  (B_*S_)      // 4096 rows total

// ---------------- scratch (device globals; no allocation allowed) ----------------
__device__ float g_Q[(size_t)M_*D_];                 // fp32 proj out (pre-rope)
__device__ float g_K[(size_t)M_*D_];
__device__ float g_P[(size_t)B_*H_*S_*S_];           // fp32 scores
__device__ float g_cos[S_*64];
__device__ float g_sin[S_*64];

__device__ __nv_bfloat16 g_xh[(size_t)M_*D_],  g_xl[(size_t)M_*D_];
__device__ __nv_bfloat16 g_Wqh[(size_t)D_*D_], g_Wql[(size_t)D_*D_];
__device__ __nv_bfloat16 g_Wkh[(size_t)D_*D_], g_Wkl[(size_t)D_*D_];
__device__ __nv_bfloat16 g_Wvh[(size_t)D_*D_], g_Wvl[(size_t)D_*D_];
__device__ __nv_bfloat16 g_Woh[(size_t)D_*D_], g_Wol[(size_t)D_*D_];
__device__ __nv_bfloat16 g_Qh[(size_t)M_*D_],  g_Ql[(size_t)M_*D_];
__device__ __nv_bfloat16 g_Kh[(size_t)M_*D_],  g_Kl[(size_t)M_*D_];
__device__ __nv_bfloat16 g_Vh[(size_t)M_*D_],  g_Vl[(size_t)M_*D_];
__device__ __nv_bfloat16 g_Ph[(size_t)B_*H_*S_*S_], g_Pl[(size_t)B_*H_*S_*S_];
__device__ __nv_bfloat16 g_AOh[(size_t)M_*D_], g_AOl[(size_t)M_*D_];

// ---------------- helpers ---------------------------------------------------------
__device__ __forceinline__ uint32_t smem_u32(const void* p) {
    return (uint32_t)__cvta_generic_to_shared(p);
}
__device__ __forceinline__ void cpa16(uint32_t dst, const void* src) {
    asm volatile("cp.async.cg.shared.global [%0],[%1],16;" :: "r"(dst), "l"(src));
}
__device__ __forceinline__ void cpa_commit() { asm volatile("cp.async.commit_group;"); }
template<int N> __device__ __forceinline__ void cpa_wait() {
    asm volatile("cp.async.wait_group %0;" :: "n"(N));
}
__device__ __forceinline__ void ldsm4(uint32_t r[4], uint32_t addr) {
    asm volatile("ldmatrix.sync.aligned.m8n8.x4.shared.b16 {%0,%1,%2,%3},[%4];"
                 : "=r"(r[0]), "=r"(r[1]), "=r"(r[2]), "=r"(r[3]) : "r"(addr));
}
__device__ __forceinline__ void ldsm4t(uint32_t r[4], uint32_t addr) {
    asm volatile("ldmatrix.sync.aligned.m8n8.x4.trans.shared.b16 {%0,%1,%2,%3},[%4];"
                 : "=r"(r[0]), "=r"(r[1]), "=r"(r[2]), "=r"(r[3]) : "r"(addr));
}
__device__ __forceinline__ void mma_bf16(float d[4], const uint32_t a[4], const uint32_t b[2]) {
    asm volatile(
        "mma.sync.aligned.m16n8k16.row.col.f32.bf16.bf16.f32 "
        "{%0,%1,%2,%3},{%4,%5,%6,%7},{%8,%9},{%0,%1,%2,%3};"
        : "+f"(d[0]), "+f"(d[1]), "+f"(d[2]), "+f"(d[3])
        : "r"(a[0]), "r"(a[1]), "r"(a[2]), "r"(a[3]), "r"(b[0]), "r"(b[1]));
}
__device__ __forceinline__ void split2(float x0, float x1, uint32_t &h, uint32_t &l) {
    __nv_bfloat16 h0 = __float2bfloat16(x0);
    __nv_bfloat16 h1 = __float2bfloat16(x1);
    __nv_bfloat16 l0 = __float2bfloat16(x0 - __bfloat162float(h0));
    __nv_bfloat16 l1 = __float2bfloat16(x1 - __bfloat162float(h1));
    __nv_bfloat162 hp = __halves2bfloat162(h0, h1);
    __nv_bfloat162 lp = __halves2bfloat162(l0, l1);
    h = *reinterpret_cast<uint32_t*>(&hp);
    l = *reinterpret_cast<uint32_t*>(&lp);
}

// ---------------- elementwise fp32 -> (hi,lo) convert -----------------------------
__global__ __launch_bounds__(256)
void split_arr(const float4* __restrict__ src,
               uint2* __restrict__ h, uint2* __restrict__ l, int n4)
{
    int i = blockIdx.x * blockDim.x + threadIdx.x;
    if (i >= n4) return;
    float4 v = src[i];
    uint32_t h0, l0, h1, l1;
    split2(v.x, v.y, h0, l0);
    split2(v.z, v.w, h1, l1);
    h[i] = make_uint2(h0, h1);
    l[i] = make_uint2(l0, l1);
}

// ============================================================================
// BIG-TILE projection GEMM: C = A * B^T, pre-split bf16 planar hi/lo.
// CTA tile 256x128, k-tile 64, 2-stage cp.async. 256 threads,
// 8 warps in 4m x 2n grid, warp tile 64x64.
// smem/stage: Ah 32K | Al 32K | Bh 16K | Bl 16K = 96KB; 2 stages = 192KB.
// outSplit: 0 -> C fp32 ; 1 -> Ch/Cl bf16.
// ============================================================================
__global__ __launch_bounds__(256)
void gemm_big(const __nv_bfloat16* __restrict__ Agh, const __nv_bfloat16* __restrict__ Agl,
              const __nv_bfloat16* __restrict__ Bgh, const __nv_bfloat16* __restrict__ Bgl,
              float* __restrict__ C,
              __nv_bfloat16* __restrict__ Ch, __nv_bfloat16* __restrict__ Cl,
              int K, int lda, int ldb, int ldc, int outSplit)
{
    int rowBase = blockIdx.y * 256;
    int colBase = blockIdx.x * 128;

    extern __shared__ __align__(16) char sraw[];
    uint32_t sb = smem_u32(sraw);

    int tid = threadIdx.x, lane = tid & 31, w = tid >> 5;
    int wm = w >> 1, wn = w & 1;
    int lr = lane & 7, grp = lane >> 3;

    int agk = grp >> 1;                         // A k-chunk select
    uint32_t arow[4], arx[4];
    #pragma unroll
    for (int s = 0; s < 4; s++) {
        int r = wm * 64 + s * 16 + ((grp & 1) << 3) + lr;
        arow[s] = (uint32_t)r << 7;
        arx[s]  = r & 7;
    }
    int bgk = grp & 1;                          // B k-chunk select
    uint32_t brow[4], brx[4];
    #pragma unroll
    for (int p = 0; p < 4; p++) {
        int r = wn * 64 + p * 16 + ((grp >> 1) << 3) + lr;
        brow[p] = (uint32_t)r << 7;
        brx[p]  = r & 7;
    }

    float acc[4][8][4];
    #pragma unroll
    for (int s = 0; s < 4; s++)
        #pragma unroll
        for (int n = 0; n < 8; n++)
            #pragma unroll
            for (int j = 0; j < 4; j++) acc[s][n][j] = 0.f;

    int T = K >> 6;

    auto issue = [&](int t, int stg) {
        uint32_t base = sb + (uint32_t)stg * 98304u;
        int k0 = t << 6;
        #pragma unroll
        for (int i = 0; i < 8; i++) {           // A: 256 rows x 8 chunks (hi+lo)
            int id = tid + (i << 8);
            int r = id >> 3, c = id & 7;
            uint32_t dst = base + ((uint32_t)r << 7) + (uint32_t)((c ^ (r & 7)) << 4);
            cpa16(dst,           Agh + (size_t)(rowBase + r) * lda + k0 + (c << 3));
            cpa16(dst + 32768u,  Agl + (size_t)(rowBase + r) * lda + k0 + (c << 3));
        }
        #pragma unroll
        for (int i = 0; i < 4; i++) {           // B: 128 rows x 8 chunks (hi+lo)
            int id = tid + (i << 8);
            int r = id >> 3, c = id & 7;
            uint32_t dst = base + 65536u + ((uint32_t)r << 7) + (uint32_t)((c ^ (r & 7)) << 4);
            cpa16(dst,           Bgh + (size_t)(colBase + r) * ldb + k0 + (c << 3));
            cpa16(dst + 16384u,  Bgl + (size_t)(colBase + r) * ldb + k0 + (c << 3));
        }
        cpa_commit();
    };

    issue(0, 0);
    for (int t = 0; t < T; t++) {
        int stg = t & 1;
        if (t + 1 < T) { issue(t + 1, stg ^ 1); cpa_wait<1>(); }
        else          { cpa_wait<0>(); }
        __syncthreads();

        uint32_t aH = sb + (uint32_t)stg * 98304u;
        uint32_t aL = aH + 32768u;
        uint32_t bH = aH + 65536u;
        uint32_t bL = aH + 81920u;

        #pragma unroll
        for (int st = 0; st < 4; st++) {
            uint32_t Ah[4][4], Al[4][4], Bh[8][2], Bl[8][2];
            #pragma unroll
            for (int s = 0; s < 4; s++) {
                uint32_t off = arow[s] + ((((st << 1) + agk) ^ arx[s]) << 4);
                ldsm4(Ah[s], aH + off);
                ldsm4(Al[s], aL + off);
            }
            #pragma unroll
            for (int p = 0; p < 4; p++) {
                uint32_t off = brow[p] + ((((st << 1) + bgk) ^ brx[p]) << 4);
                uint32_t tr[4];
                ldsm4(tr, bH + off);
                Bh[2*p][0] = tr[0]; Bh[2*p][1] = tr[1];
                Bh[2*p+1][0] = tr[2]; Bh[2*p+1][1] = tr[3];
                ldsm4(tr, bL + off);
                Bl[2*p][0] = tr[0]; Bl[2*p][1] = tr[1];
                Bl[2*p+1][0] = tr[2]; Bl[2*p+1][1] = tr[3];
            }
            #pragma unroll
            for (int s = 0; s < 4; s++)
                #pragma unroll
                for (int n = 0; n < 8; n++) {
                    mma_bf16(acc[s][n], Ah[s], Bh[n]);
                    mma_bf16(acc[s][n], Ah[s], Bl[n]);
                    mma_bf16(acc[s][n], Al[s], Bh[n]);
                }
        }
        __syncthreads();
    }

    // ---- epilogue ----
    #pragma unroll
    for (int s = 0; s < 4; s++) {
        int r0 = rowBase + wm * 64 + s * 16 + (lane >> 2);
        #pragma unroll
        for (int n = 0; n < 8; n++) {
            int c0 = colBase + wn * 64 + n * 8 + ((lane & 3) << 1);
            if (!outSplit) {
                *(float2*)&C[(size_t)r0 * ldc + c0]       = make_float2(acc[s][n][0], acc[s][n][1]);
                *(float2*)&C[(size_t)(r0 + 8) * ldc + c0] = make_float2(acc[s][n][2], acc[s][n][3]);
            } else {
                uint32_t h0, l0, h1, l1;
                split2(acc[s][n][0], acc[s][n][1], h0, l0);
                split2(acc[s][n][2], acc[s][n][3], h1, l1);
                *(uint32_t*)&Ch[(size_t)r0 * ldc + c0]       = h0;
                *(uint32_t*)&Cl[(size_t)r0 * ldc + c0]       = l0;
                *(uint32_t*)&Ch[(size_t)(r0 + 8) * ldc + c0] = h1;
                *(uint32_t*)&Cl[(size_t)(r0 + 8) * ldc + c0] = l1;
            }
        }
    }
}

// ============================================================================
// C = A * B^T batched (QK^T): 128x128 CTA, 512 thr, 16 warps 32x32. (R8 proven)
// ============================================================================
__global__ __launch_bounds__(512)
void gemm_bs(const __nv_bfloat16* __restrict__ Agh, const __nv_bfloat16* __restrict__ Agl,
             const __nv_bfloat16* __restrict__ Bgh, const __nv_bfloat16* __restrict__ Bgl,
             float* __restrict__ C,
             int K, int lda, int ldb, int ldc,
             int zdiv,
             long long sAo, long long sAi,
             long long sBo, long long sBi,
             long long sCo, long long sCi,
             int causalSkip)
{
    int z = blockIdx.z;
    int zo = z / zdiv, zi = z - zo * zdiv;
    long long aOff = zo * sAo + zi * sAi;
    long long bOff = zo * sBo + zi * sBi;
    long long cOff = zo * sCo + zi * sCi;
    Agh += aOff; Agl += aOff;
    Bgh += bOff; Bgl += bOff;

    int rowBase = blockIdx.y * 128;
    int colBase = blockIdx.x * 128;
    if (causalSkip && colBase > rowBase) return;

    extern __shared__ __align__(16) char sraw[];
    uint32_t sb = smem_u32(sraw);

    int tid = threadIdx.x, lane = tid & 31, w = tid >> 5;
    int wm = w >> 2, wn = w & 3;
    int lr = lane & 7, grp = lane >> 3;

    int agk = grp >> 1;
    uint32_t arow[2], arx[2];
    #pragma unroll
    for (int s = 0; s < 2; s++) {
        int r = wm * 32 + s * 16 + ((grp & 1) << 3) + lr;
        arow[s] = (uint32_t)r << 7;
        arx[s]  = r & 7;
    }
    int bgk = grp & 1;
    uint32_t brow[2], brx[2];
    #pragma unroll
    for (int p = 0; p < 2; p++) {
        int r = wn * 32 + p * 16 + ((grp >> 1) << 3) + lr;
        brow[p] = (uint32_t)r << 7;
        brx[p]  = r & 7;
    }

    float acc[2][4][4];
    #pragma unroll
    for (int s = 0; s < 2; s++)
        #pragma unroll
        for (int n = 0; n < 4; n++)
            #pragma unroll
            for (int j = 0; j < 4; j++) acc[s][n][j] = 0.f;

    int T = K >> 6;

    auto issue = [&](int t, int stg) {
        uint32_t base = sb + (uint32_t)stg * 65536u;
        int k0 = t << 6;
        #pragma unroll
        for (int i = 0; i < 2; i++) {
            int id = tid + (i << 9);
            int r = id >> 3, c = id & 7;
            uint32_t dst = base + ((uint32_t)r << 7) + (uint32_t)((c ^ (r & 7)) << 4);
            cpa16(dst,           Agh + (size_t)(rowBase + r) * lda + k0 + (c << 3));
            cpa16(dst + 16384u,  Agl + (size_t)(rowBase + r) * lda + k0 + (c << 3));
        }
        #pragma unroll
        for (int i = 0; i < 2; i++) {
            int id = tid + (i << 9);
            int r = id >> 3, c = id & 7;
            uint32_t dst = base + 32768u + ((uint32_t)r << 7) + (uint32_t)((c ^ (r & 7)) << 4);
            cpa16(dst,           Bgh + (size_t)(colBase + r) * ldb + k0 + (c << 3));
            cpa16(dst + 16384u,  Bgl + (size_t)(colBase + r) * ldb + k0 + (c << 3));
        }
        cpa_commit();
    };

    issue(0, 0);
    for (int t = 0; t < T; t++) {
        int stg = t & 1;
        if (t + 1 < T) { issue(t + 1, stg ^ 1); cpa_wait<1>(); }
        else          { cpa_wait<0>(); }
        __syncthreads();

        uint32_t aH = sb + (uint32_t)stg * 65536u;
        uint32_t aL = aH + 16384u;
        uint32_t bH = aH + 32768u;
        uint32_t bL = aH + 49152u;

        #pragma unroll
        for (int st = 0; st < 4; st++) {
            uint32_t Ah[2][4], Al[2][4], Bh[4][2], Bl[4][2];
            #pragma unroll
            for (int s = 0; s < 2; s++) {
                uint32_t off = arow[s] + ((((st << 1) + agk) ^ arx[s]) << 4);
                ldsm4(Ah[s], aH + off);
                ldsm4(Al[s], aL + off);
            }
            #pragma unroll
            for (int p = 0; p < 2; p++) {
                uint32_t off = brow[p] + ((((st << 1) + bgk) ^ brx[p]) << 4);
                uint32_t tr[4];
                ldsm4(tr, bH + off);
                Bh[2*p][0] = tr[0]; Bh[2*p][1] = tr[1];
                Bh[2*p+1][0] = tr[2]; Bh[2*p+1][1] = tr[3];
                ldsm4(tr, bL + off);
                Bl[2*p][0] = tr[0]; Bl[2*p][1] = tr[1];
                Bl[2*p+1][0] = tr[2]; Bl[2*p+1][1] = tr[3];
            }
            #pragma unroll
            for (int s = 0; s < 2; s++)
                #pragma unroll
                for (int n = 0; n < 4; n++) {
                    mma_bf16(acc[s][n], Ah[s], Bh[n]);
                    mma_bf16(acc[s][n], Ah[s], Bl[n]);
                    mma_bf16(acc[s][n], Al[s], Bh[n]);
                }
        }
        __syncthreads();
    }

    #pragma unroll
    for (int s = 0; s < 2; s++) {
        int r0 = rowBase + wm * 32 + s * 16 + (lane >> 2);
        #pragma unroll
        for (int n = 0; n < 4; n++) {
            int c0 = colBase + wn * 32 + n * 8 + ((lane & 3) << 1);
            float* Cb = C + cOff;
            *(float2*)&Cb[(size_t)r0 * ldc + c0]       = make_float2(acc[s][n][0], acc[s][n][1]);
            *(float2*)&Cb[(size_t)(r0 + 8) * ldc + c0] = make_float2(acc[s][n][2], acc[s][n][3]);
        }
    }
}

// ============================================================================
// AO = P * V (R8 proven): 512 thr, 16 warps 32x32, causal-truncated k loop.
// ============================================================================
__global__ __launch_bounds__(512)
void gemm_pv()
{
    int z = blockIdx.z;
    int b = z >> 4, h = z & 15;
    const __nv_bfloat16* __restrict__ Pzh = g_Ph + (size_t)z * S_ * S_;
    const __nv_bfloat16* __restrict__ Pzl = g_Pl + (size_t)z * S_ * S_;
    const __nv_bfloat16* __restrict__ Vzh = g_Vh + (size_t)b * S_ * D_ + h * HD_;
    const __nv_bfloat16* __restrict__ Vzl = g_Vl + (size_t)b * S_ * D_ + h * HD_;
    __nv_bfloat16* __restrict__ Czh = g_AOh + (size_t)b * S_ * D_ + h * HD_;
    __nv_bfloat16* __restrict__ Czl = g_AOl + (size_t)b * S_ * D_ + h * HD_;

    int rowBase = blockIdx.y * 128;

    extern __shared__ __align__(16) char sraw[];
    uint32_t sb = smem_u32(sraw);

    int tid = threadIdx.x, lane = tid & 31, w = tid >> 5;
    int wm = w >> 2, wn = w & 3;
    int lr = lane & 7, grp = lane >> 3;

    int agk = grp >> 1;
    uint32_t arow[2], arx[2];
    #pragma unroll
    for (int s = 0; s < 2; s++) {
        int r = wm * 32 + s * 16 + ((grp & 1) << 3) + lr;
        arow[s] = (uint32_t)r << 7;
        arx[s]  = r & 7;
    }
    int krb = ((grp & 1) << 3) + lr;
    uint32_t bvoff[2];
    #pragma unroll
    for (int p = 0; p < 2; p++) {
        int nc = wn * 4 + p * 2 + (grp >> 1);
        bvoff[p] = ((uint32_t)krb << 8) + (uint32_t)((nc ^ (krb & 7)) << 4);
    }

    float acc[2][4][4];
    #pragma unroll
    for (int s = 0; s < 2; s++)
        #pragma unroll
        for (int n = 0; n < 4; n++)
            #pragma unroll
            for (int j = 0; j < 4; j++) acc[s][n][j] = 0.f;

    int T = (rowBase >> 6) + 2;

    auto issue = [&](int t, int stg) {
        uint32_t base = sb + (uint32_t)stg * 65536u;
        int k0 = t << 6;
        #pragma unroll
        for (int i = 0; i < 2; i++) {
            int id = tid + (i << 9);
            int r = id >> 3, c = id & 7;
            uint32_t dst = base + ((uint32_t)r << 7) + (uint32_t)((c ^ (r & 7)) << 4);
            cpa16(dst,           Pzh + (size_t)(rowBase + r) * S_ + k0 + (c << 3));
            cpa16(dst + 16384u,  Pzl + (size_t)(rowBase + r) * S_ + k0 + (c << 3));
        }
        #pragma unroll
        for (int i = 0; i < 2; i++) {
            int id = tid + (i << 9);
            int kr = id >> 4, c = id & 15;
            uint32_t dst = base + 32768u + ((uint32_t)kr << 8) + (uint32_t)((c ^ (kr & 7)) << 4);
            cpa16(dst,           Vzh + (size_t)(k0 + kr) * D_ + (c << 3));
            cpa16(dst + 16384u,  Vzl + (size_t)(k0 + kr) * D_ + (c << 3));
        }
        cpa_commit();
    };

    issue(0, 0);
    for (int t = 0; t < T; t++) {
        int stg = t & 1;
        if (t + 1 < T) { issue(t + 1, stg ^ 1); cpa_wait<1>(); }
        else          { cpa_wait<0>(); }
        __syncthreads();

        uint32_t aH = sb + (uint32_t)stg * 65536u;
        uint32_t aL = aH + 16384u;
        uint32_t bH = aH + 32768u;
        uint32_t bL = aH + 49152u;

        #pragma unroll
        for (int st = 0; st < 4; st++) {
            uint32_t Ah[2][4], Al[2][4], Bh[4][2], Bl[4][2];
            #pragma unroll
            for (int s = 0; s < 2; s++) {
                uint32_t off = arow[s] + ((((st << 1) + agk) ^ arx[s]) << 4);
                ldsm4(Ah[s], aH + off);
                ldsm4(Al[s], aL + off);
            }
            #pragma unroll
            for (int p = 0; p < 2; p++) {
                uint32_t off = ((uint32_t)st << 12) + bvoff[p];
                uint32_t tr[4];
                ldsm4t(tr, bH + off);
                Bh[2*p][0] = tr[0]; Bh[2*p][1] = tr[1];
                Bh[2*p+1][0] = tr[2]; Bh[2*p+1][1] = tr[3];
                ldsm4t(tr, bL + off);
                Bl[2*p][0] = tr[0]; Bl[2*p][1] = tr[1];
                Bl[2*p+1][0] = tr[2]; Bl[2*p+1][1] = tr[3];
            }
            #pragma unroll
            for (int s = 0; s < 2; s++)
                #pragma unroll
                for (int n = 0; n < 4; n++) {
                    mma_bf16(acc[s][n], Ah[s], Bh[n]);
                    mma_bf16(acc[s][n], Ah[s], Bl[n]);
                    mma_bf16(acc[s][n], Al[s], Bh[n]);
                }
        }
        __syncthreads();
    }

    #pragma unroll
    for (int s = 0; s < 2; s++) {
        int r0 = rowBase + wm * 32 + s * 16 + (lane >> 2);
        #pragma unroll
        for (int n = 0; n < 4; n++) {
            int c0 = wn * 32 + n * 8 + ((lane & 3) << 1);
            uint32_t h0, l0, h1, l1;
            split2(acc[s][n][0], acc[s][n][1], h0, l0);
            split2(acc[s][n][2], acc[s][n][3], h1, l1);
            *(uint32_t*)&Czh[(size_t)r0 * D_ + c0]       = h0;
            *(uint32_t*)&Czl[(size_t)r0 * D_ + c0]       = l0;
            *(uint32_t*)&Czh[(size_t)(r0 + 8) * D_ + c0] = h1;
            *(uint32_t*)&Czl[(size_t)(r0 + 8) * D_ + c0] = l1;
        }
    }
}

// ---------------- RoPE tables -----------------------------------------------------
__global__ void rope_tables()
{
    int i = blockIdx.x * blockDim.x + threadIdx.x;
    if (i >= S_ * 64) return;
    int d = i & 63;
    int s = i >> 6;
    double inv = exp2(-(double)d / 64.0 * 13.287712379549449);   // log2(10000)
    double ang = (double)s * inv;
    g_cos[i] = (float)cos(ang);
    g_sin[i] = (float)sin(ang);
}

// ---------------- RoPE apply: fp32 Q/K -> split bf16 (scale folded into Q) -------
__global__ void rope_apply()
{
    size_t i = (size_t)blockIdx.x * blockDim.x + threadIdx.x;
    if (i >= (size_t)M_ * H_ * 64) return;
    int d = (int)(i & 63);
    int h = (int)((i >> 6) & (H_ - 1));
    int m = (int)(i >> 10);
    int s = m & (S_ - 1);
    float c  = g_cos[s * 64 + d];
    float sn = g_sin[s * 64 + d];
    const float scale = 0.08838834764831845f;   // 1/sqrt(128)
    size_t base = (size_t)m * D_ + h * HD_ + d;

    float q1 = g_Q[base], q2 = g_Q[base + 64];
    float qr1 = (q1 * c - q2 * sn) * scale;
    float qr2 = (q2 * c + q1 * sn) * scale;
    __nv_bfloat16 qh1 = __float2bfloat16(qr1);
    __nv_bfloat16 qh2 = __float2bfloat16(qr2);
    g_Qh[base]      = qh1; g_Ql[base]      = __float2bfloat16(qr1 - __bfloat162float(qh1));
    g_Qh[base + 64] = qh2; g_Ql[base + 64] = __float2bfloat16(qr2 - __bfloat162float(qh2));

    float k1 = g_K[base], k2 = g_K[base + 64];
    float kr1 = k1 * c - k2 * sn;
    float kr2 = k2 * c + k1 * sn;
    __nv_bfloat16 kh1 = __float2bfloat16(kr1);
    __nv_bfloat16 kh2 = __float2bfloat16(kr2);
    g_Kh[base]      = kh1; g_Kl[base]      = __float2bfloat16(kr1 - __bfloat162float(kh1));
    g_Kh[base + 64] = kh2; g_Kl[base + 64] = __float2bfloat16(kr2 - __bfloat162float(kh2));
}

// ---------------- causal softmax: fp32 scores -> split bf16 probs (zero-padded) ---
__global__ void softmax_rows()
{
    int gw   = (blockIdx.x * blockDim.x + threadIdx.x) >> 5;
    int lane = threadIdx.x & 31;
    if (gw >= B_ * H_ * S_) return;
    int s  = gw & (S_ - 1);
    int bh = gw >> 11;
    const float* row = g_P + (size_t)bh * S_ * S_ + (size_t)s * S_;
    __nv_bfloat16* oh = g_Ph + (size_t)bh * S_ * S_ + (size_t)s * S_;
    __nv_bfloat16* ol = g_Pl + (size_t)bh * S_ * S_ + (size_t)s * S_;
    int n = s + 1;
    int padEnd = ((s >> 7) + 1) << 7;

    float mx = -3.4e38f;
    for (int j = lane; j < n; j += 32) mx = fmaxf(mx, row[j]);
    #pragma unroll
    for (int o = 16; o; o >>= 1) mx = fmaxf(mx, __shfl_xor_sync(0xffffffffu, mx, o));

    float sum = 0.f;
    for (int j = lane; j < n; j += 32) sum += __expf(row[j] - mx);
    #pragma unroll
    for (int o = 16; o; o >>= 1) sum += __shfl_xor_sync(0xffffffffu, sum, o);

    float inv = 1.f / sum;
    for (int j = lane; j < padEnd; j += 32) {
        float p = (j < n) ? __expf(row[j] - mx) * inv : 0.f;
        __nv_bfloat16 ph = __float2bfloat16(p);
        oh[j] = ph;
        ol[j] = __float2bfloat16(p - __bfloat162float(ph));
    }
}

// ---------------- launch ----------------------------------------------------------
extern "C" void kernel_launch(void* const* d_in, const int* in_sizes, int n_in,
                              void* d_out, int out_size)
{
    const float* x  = (const float*)d_in[0];
    const float* Wq = (const float*)d_in[1];
    const float* Wk = (const float*)d_in[2];
    const float* Wv = (const float*)d_in[3];
    const float* Wo = (const float*)d_in[4];
    float* out = (float*)d_out;

    float *Qp, *Kp, *Pp;
    cudaGetSymbolAddress((void**)&Qp, g_Q);
    cudaGetSymbolAddress((void**)&Kp, g_K);
    cudaGetSymbolAddress((void**)&Pp, g_P);
    __nv_bfloat16 *xh, *xl, *Wqh, *Wql, *Wkh, *Wkl, *Wvh, *Wvl, *Woh, *Wol;
    __nv_bfloat16 *Qh, *Ql, *Kh, *Kl, *Vh, *Vl, *AOh, *AOl;
    cudaGetSymbolAddress((void**)&xh,  g_xh);  cudaGetSymbolAddress((void**)&xl,  g_xl);
    cudaGetSymbolAddress((void**)&Wqh, g_Wqh); cudaGetSymbolAddress((void**)&Wql, g_Wql);
    cudaGetSymbolAddress((void**)&Wkh, g_Wkh); cudaGetSymbolAddress((void**)&Wkl, g_Wkl);
    cudaGetSymbolAddress((void**)&Wvh, g_Wvh); cudaGetSymbolAddress((void**)&Wvl, g_Wvl);
    cudaGetSymbolAddress((void**)&Woh, g_Woh); cudaGetSymbolAddress((void**)&Wol, g_Wol);
    cudaGetSymbolAddress((void**)&Qh,  g_Qh);  cudaGetSymbolAddress((void**)&Ql,  g_Ql);
    cudaGetSymbolAddress((void**)&Kh,  g_Kh);  cudaGetSymbolAddress((void**)&Kl,  g_Kl);
    cudaGetSymbolAddress((void**)&Vh,  g_Vh);  cudaGetSymbolAddress((void**)&Vl,  g_Vl);
    cudaGetSymbolAddress((void**)&AOh, g_AOh); cudaGetSymbolAddress((void**)&AOl, g_AOl);

    cudaFuncSetAttribute(gemm_big, cudaFuncAttributeMaxDynamicSharedMemorySize, 196608);
    cudaFuncSetAttribute(gemm_bs,  cudaFuncAttributeMaxDynamicSharedMemorySize, 131072);
    cudaFuncSetAttribute(gemm_pv,  cudaFuncAttributeMaxDynamicSharedMemorySize, 131072);

    dim3 blk256(256), blk512(512);

    // 0) split inputs
    {
        int n4x = (int)((size_t)M_ * D_ / 4);
        int n4w = (int)((size_t)D_ * D_ / 4);
        split_arr<<<(n4x + 255) / 256, blk256>>>((const float4*)x,  (uint2*)xh,  (uint2*)xl,  n4x);
        split_arr<<<(n4w + 255) / 256, blk256>>>((const float4*)Wq, (uint2*)Wqh, (uint2*)Wql, n4w);
        split_arr<<<(n4w + 255) / 256, blk256>>>((const float4*)Wk, (uint2*)Wkh, (uint2*)Wkl, n4w);
        split_arr<<<(n4w + 255) / 256, blk256>>>((const float4*)Wv, (uint2*)Wvh, (uint2*)Wvl, n4w);
        split_arr<<<(n4w + 255) / 256, blk256>>>((const float4*)Wo, (uint2*)Woh, (uint2*)Wol, n4w);
    }

    // 1) projections (big-tile): Q,K fp32 (rope follows) ; V split direct
    dim3 gProj(D_ / 128, M_ / 256, 1);
    gemm_big<<<gProj, blk256, 196608>>>(xh, xl, Wqh, Wql, Qp, 0, 0,
                                        D_, D_, D_, D_, 0);
    gemm_big<<<gProj, blk256, 196608>>>(xh, xl, Wkh, Wkl, Kp, 0, 0,
                                        D_, D_, D_, D_, 0);
    gemm_big<<<gProj, blk256, 196608>>>(xh, xl, Wvh, Wvl, 0, Vh, Vl,
                                        D_, D_, D_, D_, 1);

    // 2) RoPE
    rope_tables<<<(S_ * 64 + 255) / 256, blk256>>>();
    rope_apply<<<((size_t)M_ * H_ * 64 + 255) / 256, blk256>>>();

    // 3) scores = Q K^T per (b,h), causal block skip, fp32 out
    dim3 gScore(S_ / 128, S_ / 128, B_ * H_);
    gemm_bs<<<gScore, blk512, 131072>>>(Qh, Ql, Kh, Kl, Pp,
                                        HD_, D_, D_, S_,
                                        H_,
                                        (long long)S_ * D_, (long long)HD_,
                                        (long long)S_ * D_, (long long)HD_,
                                        (long long)H_ * S_ * S_, (long long)S_ * S_,
                                        1);

    // 4) softmax -> split bf16 probs, zero-padded to 128 boundary
    {
        long long warps = (long long)B_ * H_ * S_;
        long long threads = warps * 32;
        softmax_rows<<<(unsigned)((threads + 255) / 256), blk256>>>();
    }

    // 5) attn_out = P * V -> split bf16
    dim3 gPV(1, S_ / 128, B_ * H_);
    gemm_pv<<<gPV, blk512, 131072>>>();

    // 6) out = AO * Wo^T (big-tile), fp32 out
    gemm_big<<<gProj, blk256, 196608>>>(AOh, AOl, Woh, Wol, out, 0, 0,
                                        D_, D_, D_, D_, 0);
}

// round 11
// speedup vs baseline: 3.9723x; 1.1172x over previous
#include <cuda_runtime.h>
#include <cuda_bf16.h>
#include <math.h>
#include <stdint.h>

#define B_  2
#define S_  2048
#define D_  2048
#define H_  16
#define HD_ 128
#define M_  (B_*S_)      // 4096 rows total

// ---------------- scratch (device globals; no allocation allowed) ----------------
__device__ float g_Q[(size_t)M_*D_];                 // fp32 proj out (pre-rope)
__device__ float g_K[(size_t)M_*D_];
__device__ float g_cos[S_*64];
__device__ float g_sin[S_*64];

__device__ __nv_bfloat16 g_xh[(size_t)M_*D_],  g_xl[(size_t)M_*D_];
__device__ __nv_bfloat16 g_Wqh[(size_t)D_*D_], g_Wql[(size_t)D_*D_];
__device__ __nv_bfloat16 g_Wkh[(size_t)D_*D_], g_Wkl[(size_t)D_*D_];
__device__ __nv_bfloat16 g_Wvh[(size_t)D_*D_], g_Wvl[(size_t)D_*D_];
__device__ __nv_bfloat16 g_Woh[(size_t)D_*D_], g_Wol[(size_t)D_*D_];
__device__ __nv_bfloat16 g_Qh[(size_t)M_*D_],  g_Ql[(size_t)M_*D_];
__device__ __nv_bfloat16 g_Kh[(size_t)M_*D_],  g_Kl[(size_t)M_*D_];
__device__ __nv_bfloat16 g_Vh[(size_t)M_*D_],  g_Vl[(size_t)M_*D_];
__device__ __nv_bfloat16 g_AOh[(size_t)M_*D_], g_AOl[(size_t)M_*D_];

// ---------------- helpers ---------------------------------------------------------
__device__ __forceinline__ uint32_t smem_u32(const void* p) {
    return (uint32_t)__cvta_generic_to_shared(p);
}
__device__ __forceinline__ void cpa16(uint32_t dst, const void* src) {
    asm volatile("cp.async.cg.shared.global [%0],[%1],16;" :: "r"(dst), "l"(src));
}
__device__ __forceinline__ void cpa_commit() { asm volatile("cp.async.commit_group;"); }
template<int N> __device__ __forceinline__ void cpa_wait() {
    asm volatile("cp.async.wait_group %0;" :: "n"(N));
}
__device__ __forceinline__ void ldsm4(uint32_t r[4], uint32_t addr) {
    asm volatile("ldmatrix.sync.aligned.m8n8.x4.shared.b16 {%0,%1,%2,%3},[%4];"
                 : "=r"(r[0]), "=r"(r[1]), "=r"(r[2]), "=r"(r[3]) : "r"(addr));
}
__device__ __forceinline__ void ldsm4t(uint32_t r[4], uint32_t addr) {
    asm volatile("ldmatrix.sync.aligned.m8n8.x4.trans.shared.b16 {%0,%1,%2,%3},[%4];"
                 : "=r"(r[0]), "=r"(r[1]), "=r"(r[2]), "=r"(r[3]) : "r"(addr));
}
__device__ __forceinline__ void mma_bf16(float d[4], const uint32_t a[4], const uint32_t b[2]) {
    asm volatile(
        "mma.sync.aligned.m16n8k16.row.col.f32.bf16.bf16.f32 "
        "{%0,%1,%2,%3},{%4,%5,%6,%7},{%8,%9},{%0,%1,%2,%3};"
        : "+f"(d[0]), "+f"(d[1]), "+f"(d[2]), "+f"(d[3])
        : "r"(a[0]), "r"(a[1]), "r"(a[2]), "r"(a[3]), "r"(b[0]), "r"(b[1]));
}
__device__ __forceinline__ void split2(float x0, float x1, uint32_t &h, uint32_t &l) {
    __nv_bfloat16 h0 = __float2bfloat16(x0);
    __nv_bfloat16 h1 = __float2bfloat16(x1);
    __nv_bfloat16 l0 = __float2bfloat16(x0 - __bfloat162float(h0));
    __nv_bfloat16 l1 = __float2bfloat16(x1 - __bfloat162float(h1));
    __nv_bfloat162 hp = __halves2bfloat162(h0, h1);
    __nv_bfloat162 lp = __halves2bfloat162(l0, l1);
    h = *reinterpret_cast<uint32_t*>(&hp);
    l = *reinterpret_cast<uint32_t*>(&lp);
}

// ---------------- elementwise fp32 -> (hi,lo) convert -----------------------------
__global__ __launch_bounds__(256)
void split_arr(const float4* __restrict__ src,
               uint2* __restrict__ h, uint2* __restrict__ l, int n4)
{
    int i = blockIdx.x * blockDim.x + threadIdx.x;
    if (i >= n4) return;
    float4 v = src[i];
    uint32_t h0, l0, h1, l1;
    split2(v.x, v.y, h0, l0);
    split2(v.z, v.w, h1, l1);
    h[i] = make_uint2(h0, h1);
    l[i] = make_uint2(l0, l1);
}

// ============================================================================
// BIG-TILE projection GEMM (R9 proven): C = A * B^T, 256x128 CTA, k64, 2-stage.
// ============================================================================
__global__ __launch_bounds__(256)
void gemm_big(const __nv_bfloat16* __restrict__ Agh, const __nv_bfloat16* __restrict__ Agl,
              const __nv_bfloat16* __restrict__ Bgh, const __nv_bfloat16* __restrict__ Bgl,
              float* __restrict__ C,
              __nv_bfloat16* __restrict__ Ch, __nv_bfloat16* __restrict__ Cl,
              int K, int lda, int ldb, int ldc, int outSplit)
{
    int rowBase = blockIdx.y * 256;
    int colBase = blockIdx.x * 128;

    extern __shared__ __align__(16) char sraw[];
    uint32_t sb = smem_u32(sraw);

    int tid = threadIdx.x, lane = tid & 31, w = tid >> 5;
    int wm = w >> 1, wn = w & 1;
    int lr = lane & 7, grp = lane >> 3;

    int agk = grp >> 1;
    uint32_t arow[4], arx[4];
    #pragma unroll
    for (int s = 0; s < 4; s++) {
        int r = wm * 64 + s * 16 + ((grp & 1) << 3) + lr;
        arow[s] = (uint32_t)r << 7;
        arx[s]  = r & 7;
    }
    int bgk = grp & 1;
    uint32_t brow[4], brx[4];
    #pragma unroll
    for (int p = 0; p < 4; p++) {
        int r = wn * 64 + p * 16 + ((grp >> 1) << 3) + lr;
        brow[p] = (uint32_t)r << 7;
        brx[p]  = r & 7;
    }

    float acc[4][8][4];
    #pragma unroll
    for (int s = 0; s < 4; s++)
        #pragma unroll
        for (int n = 0; n < 8; n++)
            #pragma unroll
            for (int j = 0; j < 4; j++) acc[s][n][j] = 0.f;

    int T = K >> 6;

    auto issue = [&](int t, int stg) {
        uint32_t base = sb + (uint32_t)stg * 98304u;
        int k0 = t << 6;
        #pragma unroll
        for (int i = 0; i < 8; i++) {
            int id = tid + (i << 8);
            int r = id >> 3, c = id & 7;
            uint32_t dst = base + ((uint32_t)r << 7) + (uint32_t)((c ^ (r & 7)) << 4);
            cpa16(dst,           Agh + (size_t)(rowBase + r) * lda + k0 + (c << 3));
            cpa16(dst + 32768u,  Agl + (size_t)(rowBase + r) * lda + k0 + (c << 3));
        }
        #pragma unroll
        for (int i = 0; i < 4; i++) {
            int id = tid + (i << 8);
            int r = id >> 3, c = id & 7;
            uint32_t dst = base + 65536u + ((uint32_t)r << 7) + (uint32_t)((c ^ (r & 7)) << 4);
            cpa16(dst,           Bgh + (size_t)(colBase + r) * ldb + k0 + (c << 3));
            cpa16(dst + 16384u,  Bgl + (size_t)(colBase + r) * ldb + k0 + (c << 3));
        }
        cpa_commit();
    };

    issue(0, 0);
    for (int t = 0; t < T; t++) {
        int stg = t & 1;
        if (t + 1 < T) { issue(t + 1, stg ^ 1); cpa_wait<1>(); }
        else          { cpa_wait<0>(); }
        __syncthreads();

        uint32_t aH = sb + (uint32_t)stg * 98304u;
        uint32_t aL = aH + 32768u;
        uint32_t bH = aH + 65536u;
        uint32_t bL = aH + 81920u;

        #pragma unroll
        for (int st = 0; st < 4; st++) {
            uint32_t Ah[4][4], Al[4][4], Bh[8][2], Bl[8][2];
            #pragma unroll
            for (int s = 0; s < 4; s++) {
                uint32_t off = arow[s] + ((((st << 1) + agk) ^ arx[s]) << 4);
                ldsm4(Ah[s], aH + off);
                ldsm4(Al[s], aL + off);
            }
            #pragma unroll
            for (int p = 0; p < 4; p++) {
                uint32_t off = brow[p] + ((((st << 1) + bgk) ^ brx[p]) << 4);
                uint32_t tr[4];
                ldsm4(tr, bH + off);
                Bh[2*p][0] = tr[0]; Bh[2*p][1] = tr[1];
                Bh[2*p+1][0] = tr[2]; Bh[2*p+1][1] = tr[3];
                ldsm4(tr, bL + off);
                Bl[2*p][0] = tr[0]; Bl[2*p][1] = tr[1];
                Bl[2*p+1][0] = tr[2]; Bl[2*p+1][1] = tr[3];
            }
            #pragma unroll
            for (int s = 0; s < 4; s++)
                #pragma unroll
                for (int n = 0; n < 8; n++) {
                    mma_bf16(acc[s][n], Ah[s], Bh[n]);
                    mma_bf16(acc[s][n], Ah[s], Bl[n]);
                    mma_bf16(acc[s][n], Al[s], Bh[n]);
                }
        }
        __syncthreads();
    }

    #pragma unroll
    for (int s = 0; s < 4; s++) {
        int r0 = rowBase + wm * 64 + s * 16 + (lane >> 2);
        #pragma unroll
        for (int n = 0; n < 8; n++) {
            int c0 = colBase + wn * 64 + n * 8 + ((lane & 3) << 1);
            if (!outSplit) {
                *(float2*)&C[(size_t)r0 * ldc + c0]       = make_float2(acc[s][n][0], acc[s][n][1]);
                *(float2*)&C[(size_t)(r0 + 8) * ldc + c0] = make_float2(acc[s][n][2], acc[s][n][3]);
            } else {
                uint32_t h0, l0, h1, l1;
                split2(acc[s][n][0], acc[s][n][1], h0, l0);
                split2(acc[s][n][2], acc[s][n][3], h1, l1);
                *(uint32_t*)&Ch[(size_t)r0 * ldc + c0]       = h0;
                *(uint32_t*)&Cl[(size_t)r0 * ldc + c0]       = l0;
                *(uint32_t*)&Ch[(size_t)(r0 + 8) * ldc + c0] = h1;
                *(uint32_t*)&Cl[(size_t)(r0 + 8) * ldc + c0] = l1;
            }
        }
    }
}

// ============================================================================
// FLASH ATTENTION (fused QK^T -> online softmax -> P*V), split-bf16 3-product.
// CTA: one (b,h) and 128 q rows. 8 warps, each owns 16 q rows x full width.
// Q tile (hi/lo) resident in smem; KV tiles of 64 tokens double-buffered.
// smem: Qh 32K | Ql 32K | 2 stages x { Kh 16K | Kl 16K | Vh 16K | Vl 16K } = 192K.
// Q pre-scaled by 1/sqrt(hd) in rope_apply. Output: split bf16 AOh/AOl.
// ============================================================================
__global__ __launch_bounds__(256)
void flash_attn()
{
    int z = blockIdx.z;
    int b = z >> 4, h = z & 15;
    int qt = 15 - blockIdx.y;                 // heavy tiles first
    size_t qoff = ((size_t)(b * S_) + qt * 128) * D_ + h * HD_;
    size_t kvoff = (size_t)(b * S_) * D_ + h * HD_;
    const __nv_bfloat16* __restrict__ Qgh = g_Qh + qoff;
    const __nv_bfloat16* __restrict__ Qgl = g_Ql + qoff;
    const __nv_bfloat16* __restrict__ Kgh = g_Kh + kvoff;
    const __nv_bfloat16* __restrict__ Kgl = g_Kl + kvoff;
    const __nv_bfloat16* __restrict__ Vgh = g_Vh + kvoff;
    const __nv_bfloat16* __restrict__ Vgl = g_Vl + kvoff;
    __nv_bfloat16* __restrict__ AOh = g_AOh + qoff;
    __nv_bfloat16* __restrict__ AOl = g_AOl + qoff;

    extern __shared__ __align__(16) char sraw[];
    uint32_t sb  = smem_u32(sraw);
    uint32_t sQh = sb, sQl = sb + 32768u;

    int tid = threadIdx.x, lane = tid & 31, w = tid >> 5;
    int lr = lane & 7, grp = lane >> 3;

    // ---- load Q tile (128 rows x 16 chunks, hi+lo) ----
    #pragma unroll
    for (int i = 0; i < 8; i++) {
        int id = tid + (i << 8);
        int r = id >> 4, c = id & 15;
        uint32_t dst = sQh + ((uint32_t)r << 8) + (uint32_t)((c ^ (r & 7)) << 4);
        cpa16(dst,           Qgh + (size_t)r * D_ + (c << 3));
        cpa16(dst + 32768u,  Qgl + (size_t)r * D_ + (c << 3));
    }

    auto issueKV = [&](int kt, int stg) {
        uint32_t base = sb + 65536u + (uint32_t)stg * 65536u;
        #pragma unroll
        for (int i = 0; i < 4; i++) {
            int id = tid + (i << 8);
            int r = id >> 4, c = id & 15;
            uint32_t dst = base + ((uint32_t)r << 8) + (uint32_t)((c ^ (r & 7)) << 4);
            const __nv_bfloat16* ks = Kgh + (size_t)(kt * 64 + r) * D_ + (c << 3);
            cpa16(dst, ks);
            cpa16(dst + 16384u, Kgl + (size_t)(kt * 64 + r) * D_ + (c << 3));
            cpa16(dst + 32768u, Vgh + (size_t)(kt * 64 + r) * D_ + (c << 3));
            cpa16(dst + 49152u, Vgl + (size_t)(kt * 64 + r) * D_ + (c << 3));
        }
    };

    issueKV(0, 0);
    cpa_commit();                              // group: Q + KV0

    // per-warp fragment geometry
    int qr = 16 * w + ((grp & 1) << 3) + lr;   // A rows for ldsm
    uint32_t aoffBase = ((uint32_t)qr << 8);
    uint32_t aXor = qr & 7;

    uint32_t Ah[8][4];                          // Q hi frags, hoisted
    float accO[16][4];
    #pragma unroll
    for (int n = 0; n < 16; n++)
        #pragma unroll
        for (int j = 0; j < 4; j++) accO[n][j] = 0.f;
    float m0 = -1e30f, m1 = -1e30f, l0 = 0.f, l1 = 0.f;

    int row0 = qt * 128 + 16 * w + (lane >> 2);   // global q row (thread's first row)

    int T = 2 * qt + 2;
    for (int kt = 0; kt < T; kt++) {
        int stg = kt & 1;
        if (kt + 1 < T) { issueKV(kt + 1, stg ^ 1); cpa_commit(); cpa_wait<1>(); }
        else            { cpa_wait<0>(); }
        __syncthreads();

        if (kt == 0) {
            #pragma unroll
            for (int st = 0; st < 8; st++) {
                uint32_t off = aoffBase + ((((st << 1) + (grp >> 1)) ^ aXor) << 4);
                ldsm4(Ah[st], sQh + off);
            }
        }

        uint32_t base = sb + 65536u + (uint32_t)stg * 65536u;
        uint32_t sKh = base, sKl = base + 16384u, sVh = base + 32768u, sVl = base + 49152u;

        // ---- scores S = Q K^T (128 x 64), 3-product split ----
        float accs[8][4];
        #pragma unroll
        for (int n = 0; n < 8; n++)
            #pragma unroll
            for (int j = 0; j < 4; j++) accs[n][j] = 0.f;

        #pragma unroll
        for (int st = 0; st < 8; st++) {
            uint32_t aL[4];
            {
                uint32_t off = aoffBase + ((((st << 1) + (grp >> 1)) ^ aXor) << 4);
                ldsm4(aL, sQl + off);
            }
            #pragma unroll
            for (int p = 0; p < 4; p++) {
                int rr = p * 16 + ((grp >> 1) << 3) + lr;
                uint32_t off = ((uint32_t)rr << 8) + ((((st << 1) + (grp & 1)) ^ (rr & 7)) << 4);
                uint32_t th[4], tl[4];
                ldsm4(th, sKh + off);
                ldsm4(tl, sKl + off);
                uint32_t f0[2] = {th[0], th[1]}, f1[2] = {th[2], th[3]};
                uint32_t g0[2] = {tl[0], tl[1]}, g1[2] = {tl[2], tl[3]};
                mma_bf16(accs[2*p],   Ah[st], f0);
                mma_bf16(accs[2*p],   Ah[st], g0);
                mma_bf16(accs[2*p],   aL,     f0);
                mma_bf16(accs[2*p+1], Ah[st], f1);
                mma_bf16(accs[2*p+1], Ah[st], g1);
                mma_bf16(accs[2*p+1], aL,     f1);
            }
        }

        // ---- causal mask (only on diagonal-crossing tiles) ----
        if (kt >= 2 * qt) {
            int colb = kt * 64 + ((lane & 3) << 1);
            #pragma unroll
            for (int n = 0; n < 8; n++) {
                int c0 = colb + n * 8;
                if (c0     > row0)     accs[n][0] = -1e30f;
                if (c0 + 1 > row0)     accs[n][1] = -1e30f;
                if (c0     > row0 + 8) accs[n][2] = -1e30f;
                if (c0 + 1 > row0 + 8) accs[n][3] = -1e30f;
            }
        }

        // ---- online softmax update ----
        float mx0 = -1e30f, mx1 = -1e30f;
        #pragma unroll
        for (int n = 0; n < 8; n++) {
            mx0 = fmaxf(mx0, fmaxf(accs[n][0], accs[n][1]));
            mx1 = fmaxf(mx1, fmaxf(accs[n][2], accs[n][3]));
        }
        mx0 = fmaxf(mx0, __shfl_xor_sync(0xffffffffu, mx0, 1));
        mx0 = fmaxf(mx0, __shfl_xor_sync(0xffffffffu, mx0, 2));
        mx1 = fmaxf(mx1, __shfl_xor_sync(0xffffffffu, mx1, 1));
        mx1 = fmaxf(mx1, __shfl_xor_sync(0xffffffffu, mx1, 2));
        float nm0 = fmaxf(m0, mx0), nm1 = fmaxf(m1, mx1);
        float sf0 = __expf(m0 - nm0), sf1 = __expf(m1 - nm1);
        m0 = nm0; m1 = nm1;

        float rs0 = 0.f, rs1 = 0.f;
        #pragma unroll
        for (int n = 0; n < 8; n++) {
            accs[n][0] = __expf(accs[n][0] - nm0); rs0 += accs[n][0];
            accs[n][1] = __expf(accs[n][1] - nm0); rs0 += accs[n][1];
            accs[n][2] = __expf(accs[n][2] - nm1); rs1 += accs[n][2];
            accs[n][3] = __expf(accs[n][3] - nm1); rs1 += accs[n][3];
        }
        rs0 += __shfl_xor_sync(0xffffffffu, rs0, 1);
        rs0 += __shfl_xor_sync(0xffffffffu, rs0, 2);
        rs1 += __shfl_xor_sync(0xffffffffu, rs1, 1);
        rs1 += __shfl_xor_sync(0xffffffffu, rs1, 2);
        l0 = l0 * sf0 + rs0;
        l1 = l1 * sf1 + rs1;

        #pragma unroll
        for (int n = 0; n < 16; n++) {
            accO[n][0] *= sf0; accO[n][1] *= sf0;
            accO[n][2] *= sf1; accO[n][3] *= sf1;
        }

        // ---- O += P V, 3-product split; P frags come from accs layout ----
        #pragma unroll
        for (int kp = 0; kp < 4; kp++) {
            uint32_t ph[4], pl[4];
            split2(accs[2*kp][0],   accs[2*kp][1],   ph[0], pl[0]);
            split2(accs[2*kp][2],   accs[2*kp][3],   ph[1], pl[1]);
            split2(accs[2*kp+1][0], accs[2*kp+1][1], ph[2], pl[2]);
            split2(accs[2*kp+1][2], accs[2*kp+1][3], ph[3], pl[3]);

            int krb = ((grp & 1) << 3) + lr;
            #pragma unroll
            for (int j = 0; j < 8; j++) {
                int nc = j * 2 + (grp >> 1);
                uint32_t off = ((uint32_t)kp << 12) + ((uint32_t)krb << 8)
                             + (uint32_t)((nc ^ (krb & 7)) << 4);
                uint32_t th[4], tl[4];
                ldsm4t(th, sVh + off);
                ldsm4t(tl, sVl + off);
                uint32_t f0[2] = {th[0], th[1]}, f1[2] = {th[2], th[3]};
                uint32_t g0[2] = {tl[0], tl[1]}, g1[2] = {tl[2], tl[3]};
                mma_bf16(accO[2*j],   ph, f0);
                mma_bf16(accO[2*j],   ph, g0);
                mma_bf16(accO[2*j],   pl, f0);
                mma_bf16(accO[2*j+1], ph, f1);
                mma_bf16(accO[2*j+1], ph, g1);
                mma_bf16(accO[2*j+1], pl, f1);
            }
        }
        __syncthreads();
    }

    // ---- finalize: O /= l, write split bf16 ----
    float inv0 = 1.f / l0, inv1 = 1.f / l1;
    int lrow = 16 * w + (lane >> 2);
    #pragma unroll
    for (int n = 0; n < 16; n++) {
        int c0 = n * 8 + ((lane & 3) << 1);
        uint32_t h0, lo0, h1, lo1;
        split2(accO[n][0] * inv0, accO[n][1] * inv0, h0, lo0);
        split2(accO[n][2] * inv1, accO[n][3] * inv1, h1, lo1);
        *(uint32_t*)&AOh[(size_t)lrow * D_ + c0]       = h0;
        *(uint32_t*)&AOl[(size_t)lrow * D_ + c0]       = lo0;
        *(uint32_t*)&AOh[(size_t)(lrow + 8) * D_ + c0] = h1;
        *(uint32_t*)&AOl[(size_t)(lrow + 8) * D_ + c0] = lo1;
    }
}

// ---------------- RoPE tables -----------------------------------------------------
__global__ void rope_tables()
{
    int i = blockIdx.x * blockDim.x + threadIdx.x;
    if (i >= S_ * 64) return;
    int d = i & 63;
    int s = i >> 6;
    double inv = exp2(-(double)d / 64.0 * 13.287712379549449);   // log2(10000)
    double ang = (double)s * inv;
    g_cos[i] = (float)cos(ang);
    g_sin[i] = (float)sin(ang);
}

// ---------------- RoPE apply: fp32 Q/K -> split bf16 (scale folded into Q) -------
__global__ void rope_apply()
{
    size_t i = (size_t)blockIdx.x * blockDim.x + threadIdx.x;
    if (i >= (size_t)M_ * H_ * 64) return;
    int d = (int)(i & 63);
    int h = (int)((i >> 6) & (H_ - 1));
    int m = (int)(i >> 10);
    int s = m & (S_ - 1);
    float c  = g_cos[s * 64 + d];
    float sn = g_sin[s * 64 + d];
    const float scale = 0.08838834764831845f;   // 1/sqrt(128)
    size_t base = (size_t)m * D_ + h * HD_ + d;

    float q1 = g_Q[base], q2 = g_Q[base + 64];
    float qr1 = (q1 * c - q2 * sn) * scale;
    float qr2 = (q2 * c + q1 * sn) * scale;
    __nv_bfloat16 qh1 = __float2bfloat16(qr1);
    __nv_bfloat16 qh2 = __float2bfloat16(qr2);
    g_Qh[base]      = qh1; g_Ql[base]      = __float2bfloat16(qr1 - __bfloat162float(qh1));
    g_Qh[base + 64] = qh2; g_Ql[base + 64] = __float2bfloat16(qr2 - __bfloat162float(qh2));

    float k1 = g_K[base], k2 = g_K[base + 64];
    float kr1 = k1 * c - k2 * sn;
    float kr2 = k2 * c + k1 * sn;
    __nv_bfloat16 kh1 = __float2bfloat16(kr1);
    __nv_bfloat16 kh2 = __float2bfloat16(kr2);
    g_Kh[base]      = kh1; g_Kl[base]      = __float2bfloat16(kr1 - __bfloat162float(kh1));
    g_Kh[base + 64] = kh2; g_Kl[base + 64] = __float2bfloat16(kr2 - __bfloat162float(kh2));
}

// ---------------- launch ----------------------------------------------------------
extern "C" void kernel_launch(void* const* d_in, const int* in_sizes, int n_in,
                              void* d_out, int out_size)
{
    const float* x  = (const float*)d_in[0];
    const float* Wq = (const float*)d_in[1];
    const float* Wk = (const float*)d_in[2];
    const float* Wv = (const float*)d_in[3];
    const float* Wo = (const float*)d_in[4];
    float* out = (float*)d_out;

    float *Qp, *Kp;
    cudaGetSymbolAddress((void**)&Qp, g_Q);
    cudaGetSymbolAddress((void**)&Kp, g_K);
    __nv_bfloat16 *xh, *xl, *Wqh, *Wql, *Wkh, *Wkl, *Wvh, *Wvl, *Woh, *Wol;
    __nv_bfloat16 *Vh, *Vl, *AOh, *AOl;
    cudaGetSymbolAddress((void**)&xh,  g_xh);  cudaGetSymbolAddress((void**)&xl,  g_xl);
    cudaGetSymbolAddress((void**)&Wqh, g_Wqh); cudaGetSymbolAddress((void**)&Wql, g_Wql);
    cudaGetSymbolAddress((void**)&Wkh, g_Wkh); cudaGetSymbolAddress((void**)&Wkl, g_Wkl);
    cudaGetSymbolAddress((void**)&Wvh, g_Wvh); cudaGetSymbolAddress((void**)&Wvl, g_Wvl);
    cudaGetSymbolAddress((void**)&Woh, g_Woh); cudaGetSymbolAddress((void**)&Wol, g_Wol);
    cudaGetSymbolAddress((void**)&Vh,  g_Vh);  cudaGetSymbolAddress((void**)&Vl,  g_Vl);
    cudaGetSymbolAddress((void**)&AOh, g_AOh); cudaGetSymbolAddress((void**)&AOl, g_AOl);

    cudaFuncSetAttribute(gemm_big,   cudaFuncAttributeMaxDynamicSharedMemorySize, 196608);
    cudaFuncSetAttribute(flash_attn, cudaFuncAttributeMaxDynamicSharedMemorySize, 196608);

    dim3 blk256(256);

    // 0) split inputs
    {
        int n4x = (int)((size_t)M_ * D_ / 4);
        int n4w = (int)((size_t)D_ * D_ / 4);
        split_arr<<<(n4x + 255) / 256, blk256>>>((const float4*)x,  (uint2*)xh,  (uint2*)xl,  n4x);
        split_arr<<<(n4w + 255) / 256, blk256>>>((const float4*)Wq, (uint2*)Wqh, (uint2*)Wql, n4w);
        split_arr<<<(n4w + 255) / 256, blk256>>>((const float4*)Wk, (uint2*)Wkh, (uint2*)Wkl, n4w);
        split_arr<<<(n4w + 255) / 256, blk256>>>((const float4*)Wv, (uint2*)Wvh, (uint2*)Wvl, n4w);
        split_arr<<<(n4w + 255) / 256, blk256>>>((const float4*)Wo, (uint2*)Woh, (uint2*)Wol, n4w);
    }

    // 1) projections (big-tile): Q,K fp32 (rope follows) ; V split direct
    dim3 gProj(D_ / 128, M_ / 256, 1);
    gemm_big<<<gProj, blk256, 196608>>>(xh, xl, Wqh, Wql, Qp, 0, 0,
                                        D_, D_, D_, D_, 0);
    gemm_big<<<gProj, blk256, 196608>>>(xh, xl, Wkh, Wkl, Kp, 0, 0,
                                        D_, D_, D_, D_, 0);
    gemm_big<<<gProj, blk256, 196608>>>(xh, xl, Wvh, Wvl, 0, Vh, Vl,
                                        D_, D_, D_, D_, 1);

    // 2) RoPE
    rope_tables<<<(S_ * 64 + 255) / 256, blk256>>>();
    rope_apply<<<((size_t)M_ * H_ * 64 + 255) / 256, blk256>>>();

    // 3) fused attention: QK^T + online softmax + P*V
    dim3 gF(1, S_ / 128, B_ * H_);
    flash_attn<<<gF, blk256, 196608>>>();

    // 4) out = AO * Wo^T (big-tile), fp32 out
    gemm_big<<<gProj, blk256, 196608>>>(AOh, AOl, Woh, Wol, out, 0, 0,
                                        D_, D_, D_, D_, 0);
}